// round 2
// baseline (speedup 1.0000x reference)
#include <cuda_runtime.h>

// ---------------------------------------------------------------------------
// Problem constants
// ---------------------------------------------------------------------------
namespace {
constexpr int B  = 8;
constexpr int T  = 2048;
constexpr int D  = 1024;
constexpr int H  = 16;
constexpr int NL = 4;
constexpr int DK = 64;         // D / H
constexpr int M  = B * T;      // 16384 rows
constexpr int F  = 4 * D;      // 4096 ffn hidden
}

// ---------------------------------------------------------------------------
// Scratch (static device memory — no allocations allowed)
// ---------------------------------------------------------------------------
__device__ float g_h  [(size_t)M * D];   // LN output / attn output (reused)
__device__ float g_q  [(size_t)M * D];
__device__ float g_k  [(size_t)M * D];
__device__ float g_v  [(size_t)M * D];
__device__ float g_ffn[(size_t)M * F];
__device__ float g_kv  [B * H * DK * DK];
__device__ float g_ksum[B * H * DK];

// ---------------------------------------------------------------------------
// Embed: x = sqrt(D) * x_in + sinusoidal_pos_emb(t, d)
// ---------------------------------------------------------------------------
__global__ void embed_kernel(const float4* __restrict__ xin, float4* __restrict__ out) {
    int i = blockIdx.x * blockDim.x + threadIdx.x;     // float4 index
    int e0 = i * 4;
    int d0 = e0 & (D - 1);
    int t  = (e0 / D) & (T - 1);
    float4 xv = xin[i];
    float pos = (float)(t + 1);
    const float nlf = -9.21034037197618f / 511.0f;     // -log(10000)/511
    float xs[4] = {xv.x, xv.y, xv.z, xv.w};
    float os[4];
#pragma unroll
    for (int j = 0; j < 4; ++j) {
        int d = d0 + j;
        float pe;
        if (d < 512) pe = sinf(pos * expf(nlf * (float)d));
        else         pe = cosf(pos * expf(nlf * (float)(d - 512)));
        os[j] = 32.0f * xs[j] + pe;
    }
    out[i] = make_float4(os[0], os[1], os[2], os[3]);
}

// ---------------------------------------------------------------------------
// LayerNorm: one block (256 threads) per row of 1024 floats
// ---------------------------------------------------------------------------
__global__ void ln_kernel(const float* __restrict__ x, const float* __restrict__ sc,
                          const float* __restrict__ bi, float* __restrict__ out) {
    int row = blockIdx.x, tid = threadIdx.x;
    const float4* xr = reinterpret_cast<const float4*>(x + (size_t)row * D);
    float4 v = xr[tid];
    float s = v.x + v.y + v.z + v.w;
    float q = v.x * v.x + v.y * v.y + v.z * v.z + v.w * v.w;
#pragma unroll
    for (int o = 16; o > 0; o >>= 1) {
        s += __shfl_xor_sync(0xffffffffu, s, o);
        q += __shfl_xor_sync(0xffffffffu, q, o);
    }
    __shared__ float ss[8], sq[8];
    if ((tid & 31) == 0) { ss[tid >> 5] = s; sq[tid >> 5] = q; }
    __syncthreads();
    s = 0.f; q = 0.f;
#pragma unroll
    for (int w = 0; w < 8; ++w) { s += ss[w]; q += sq[w]; }
    float mu  = s * (1.0f / D);
    float var = q * (1.0f / D) - mu * mu;
    float rs  = rsqrtf(var + 1e-5f);
    float4 s4 = reinterpret_cast<const float4*>(sc)[tid];
    float4 b4 = reinterpret_cast<const float4*>(bi)[tid];
    float4 o;
    o.x = (v.x - mu) * rs * s4.x + b4.x;
    o.y = (v.y - mu) * rs * s4.y + b4.y;
    o.z = (v.z - mu) * rs * s4.z + b4.z;
    o.w = (v.w - mu) * rs * s4.w + b4.w;
    reinterpret_cast<float4*>(out + (size_t)row * D)[tid] = o;
}

// ---------------------------------------------------------------------------
// Tiled SGEMM: C[M,N] = op(A[M,K] @ W[K,N] + bias)
// MODE 0: plain     1: relu     2: residual (C += ...)     3: elu(x)+1
// 128x128 block tile, BK=8, 8x8 per thread, 256 threads, double-buffered smem
// ---------------------------------------------------------------------------
template <int MODE>
__global__ void __launch_bounds__(256)
sgemm_kernel(const float* __restrict__ A, const float* __restrict__ W,
             const float* __restrict__ bias, float* __restrict__ C,
             int Mm, int Nn, int Kk) {
    constexpr int BM = 128, BN = 128, BK = 8;
    __shared__ float As[2][BK][BM];
    __shared__ float Bs[2][BK][BN];
    int tid = threadIdx.x;
    int bm = blockIdx.y * BM;
    int bn = blockIdx.x * BN;

    int arow = tid >> 1;
    int acol = (tid & 1) * 4;
    int brow = tid >> 5;
    int bcol = (tid & 31) * 4;

    const float* Ag = A + (size_t)(bm + arow) * Kk + acol;
    const float* Wg = W + (size_t)brow * Nn + bn + bcol;

    float acc[8][8] = {};

    // prologue: tile 0 -> buffer 0
    {
        float4 av = *reinterpret_cast<const float4*>(Ag);
        float4 bv = *reinterpret_cast<const float4*>(Wg);
        As[0][acol + 0][arow] = av.x;
        As[0][acol + 1][arow] = av.y;
        As[0][acol + 2][arow] = av.z;
        As[0][acol + 3][arow] = av.w;
        *reinterpret_cast<float4*>(&Bs[0][brow][bcol]) = bv;
    }
    __syncthreads();

    int trow = (tid >> 4) * 8;
    int tcol = (tid & 15) * 8;
    int nk = Kk / BK;

    for (int kt = 0; kt < nk; ++kt) {
        int cur = kt & 1;
        float4 av, bv;
        bool has_next = (kt + 1 < nk);
        if (has_next) {
            av = *reinterpret_cast<const float4*>(Ag + (size_t)(kt + 1) * BK);
            bv = *reinterpret_cast<const float4*>(Wg + (size_t)(kt + 1) * BK * Nn);
        }
#pragma unroll
        for (int kk = 0; kk < BK; ++kk) {
            float4 a0 = *reinterpret_cast<const float4*>(&As[cur][kk][trow]);
            float4 a1 = *reinterpret_cast<const float4*>(&As[cur][kk][trow + 4]);
            float4 b0 = *reinterpret_cast<const float4*>(&Bs[cur][kk][tcol]);
            float4 b1 = *reinterpret_cast<const float4*>(&Bs[cur][kk][tcol + 4]);
            float ar[8] = {a0.x, a0.y, a0.z, a0.w, a1.x, a1.y, a1.z, a1.w};
            float br[8] = {b0.x, b0.y, b0.z, b0.w, b1.x, b1.y, b1.z, b1.w};
#pragma unroll
            for (int i = 0; i < 8; ++i)
#pragma unroll
                for (int j = 0; j < 8; ++j)
                    acc[i][j] = fmaf(ar[i], br[j], acc[i][j]);
        }
        if (has_next) {
            int nxt = cur ^ 1;
            As[nxt][acol + 0][arow] = av.x;
            As[nxt][acol + 1][arow] = av.y;
            As[nxt][acol + 2][arow] = av.z;
            As[nxt][acol + 3][arow] = av.w;
            *reinterpret_cast<float4*>(&Bs[nxt][brow][bcol]) = bv;
            __syncthreads();
        }
    }

    // epilogue
    float bb[8];
#pragma unroll
    for (int j = 0; j < 8; ++j) bb[j] = bias[bn + tcol + j];

#pragma unroll
    for (int i = 0; i < 8; ++i) {
        float* Crow = C + (size_t)(bm + trow + i) * Nn + bn + tcol;
        float v[8];
#pragma unroll
        for (int j = 0; j < 8; ++j) v[j] = acc[i][j] + bb[j];
        if (MODE == 1) {
#pragma unroll
            for (int j = 0; j < 8; ++j) v[j] = fmaxf(v[j], 0.f);
        } else if (MODE == 3) {
#pragma unroll
            for (int j = 0; j < 8; ++j) v[j] = (v[j] > 0.f) ? (v[j] + 1.f) : expf(v[j]);
        } else if (MODE == 2) {
            float4 e0 = *reinterpret_cast<const float4*>(Crow);
            float4 e1 = *reinterpret_cast<const float4*>(Crow + 4);
            v[0] += e0.x; v[1] += e0.y; v[2] += e0.z; v[3] += e0.w;
            v[4] += e1.x; v[5] += e1.y; v[6] += e1.z; v[7] += e1.w;
        }
        *reinterpret_cast<float4*>(Crow)     = make_float4(v[0], v[1], v[2], v[3]);
        *reinterpret_cast<float4*>(Crow + 4) = make_float4(v[4], v[5], v[6], v[7]);
    }
}

// ---------------------------------------------------------------------------
// kv[b,h,m,d] = sum_t kp[b,t,h,d] * v[b,t,h,m];  ksum[b,h,d] = sum_t kp[b,t,h,d]
// One block per (b,h), 256 threads, 4x4 accumulators, T tiled by 32.
// ---------------------------------------------------------------------------
__global__ void kv_kernel(const float* __restrict__ kp, const float* __restrict__ vv,
                          float* __restrict__ kv, float* __restrict__ ksum) {
    int bh = blockIdx.x;
    int b = bh / H, h = bh % H;
    __shared__ float ks[32][64];
    __shared__ float vs[32][64];
    int tid = threadIdx.x;
    int tm = (tid / 16) * 4;
    int td = (tid % 16) * 4;
    float acc[4][4] = {};
    float ksacc = 0.f;
    int lr = tid / 8;
    int lc = (tid % 8) * 8;
    size_t base = ((size_t)b * T * H + h) * DK;

    for (int t0 = 0; t0 < T; t0 += 32) {
        const float* kg = kp + base + (size_t)(t0 + lr) * (H * DK) + lc;
        const float* vg = vv + base + (size_t)(t0 + lr) * (H * DK) + lc;
        *reinterpret_cast<float4*>(&ks[lr][lc])     = *reinterpret_cast<const float4*>(kg);
        *reinterpret_cast<float4*>(&ks[lr][lc + 4]) = *reinterpret_cast<const float4*>(kg + 4);
        *reinterpret_cast<float4*>(&vs[lr][lc])     = *reinterpret_cast<const float4*>(vg);
        *reinterpret_cast<float4*>(&vs[lr][lc + 4]) = *reinterpret_cast<const float4*>(vg + 4);
        __syncthreads();
#pragma unroll 8
        for (int t = 0; t < 32; ++t) {
            float4 vm = *reinterpret_cast<const float4*>(&vs[t][tm]);
            float4 kd = *reinterpret_cast<const float4*>(&ks[t][td]);
            float vr[4] = {vm.x, vm.y, vm.z, vm.w};
            float kr[4] = {kd.x, kd.y, kd.z, kd.w};
#pragma unroll
            for (int i = 0; i < 4; ++i)
#pragma unroll
                for (int j = 0; j < 4; ++j)
                    acc[i][j] = fmaf(vr[i], kr[j], acc[i][j]);
        }
        if (tid < 64) {
#pragma unroll 8
            for (int t = 0; t < 32; ++t) ksacc += ks[t][tid];
        }
        __syncthreads();
    }
    float* kvb = kv + (size_t)bh * DK * DK;
#pragma unroll
    for (int i = 0; i < 4; ++i)
        *reinterpret_cast<float4*>(&kvb[(size_t)(tm + i) * DK + td]) =
            make_float4(acc[i][0], acc[i][1], acc[i][2], acc[i][3]);
    if (tid < 64) ksum[bh * DK + tid] = ksacc;
}

// ---------------------------------------------------------------------------
// out[b,t,h,m] = (sum_d qp[b,t,h,d] * kv[b,h,m,d]) / (qp . ksum + eps)
// One block per (b,h, 64-row chunk). kv transposed into smem for bcast reads.
// ---------------------------------------------------------------------------
__global__ void attnout_kernel(const float* __restrict__ qp, const float* __restrict__ kv,
                               const float* __restrict__ ksum, float* __restrict__ out) {
    constexpr int NCH = T / 64;      // 32
    int id = blockIdx.x;
    int chunk = id % NCH;
    int h = (id / NCH) % H;
    int b = id / (NCH * H);
    __shared__ float kvs[64 * 64];   // [d][m]
    __shared__ float qs[64][64];     // [r][d]
    __shared__ float kss[64];
    int tid = threadIdx.x;           // 128
    const float* kvg = kv + (size_t)(b * H + h) * (DK * DK);
#pragma unroll
    for (int it = 0; it < 8; ++it) {
        int g  = tid + it * 128;                 // float4 index 0..1023
        int m  = g >> 4;
        int d0 = (g & 15) * 4;
        float4 val = reinterpret_cast<const float4*>(kvg)[g];
        kvs[(d0 + 0) * 64 + m] = val.x;
        kvs[(d0 + 1) * 64 + m] = val.y;
        kvs[(d0 + 2) * 64 + m] = val.z;
        kvs[(d0 + 3) * 64 + m] = val.w;
    }
    if (tid < 64) kss[tid] = ksum[(b * H + h) * DK + tid];
    int t0 = chunk * 64;
    size_t qbase = (((size_t)b * T + t0) * H + h) * DK;
    {
        int r = tid >> 1;
        int c = (tid & 1) * 32;
        const float4* qg = reinterpret_cast<const float4*>(qp + qbase + (size_t)r * (H * DK) + c);
        float4* qd = reinterpret_cast<float4*>(&qs[r][c]);
#pragma unroll
        for (int j = 0; j < 8; ++j) qd[j] = qg[j];
    }
    __syncthreads();

    int mm = tid & 63;
    int hf = tid >> 6;
    for (int r = hf; r < 64; r += 2) {
        float o = 0.f, den = 0.f;
#pragma unroll
        for (int d = 0; d < 64; d += 4) {
            float4 q4 = *reinterpret_cast<const float4*>(&qs[r][d]);
            float4 k4 = *reinterpret_cast<const float4*>(&kss[d]);
            den += q4.x * k4.x + q4.y * k4.y + q4.z * k4.z + q4.w * k4.w;
            o = fmaf(q4.x, kvs[(d + 0) * 64 + mm], o);
            o = fmaf(q4.y, kvs[(d + 1) * 64 + mm], o);
            o = fmaf(q4.z, kvs[(d + 2) * 64 + mm], o);
            o = fmaf(q4.w, kvs[(d + 3) * 64 + mm], o);
        }
        out[qbase + (size_t)r * (H * DK) + mm] = o / (den + 1e-6f);
    }
}

// ---------------------------------------------------------------------------
// Host orchestration
// ---------------------------------------------------------------------------
static inline void gemm_launch(int mode, const float* A, const float* W, const float* bias,
                               float* C, int m, int n, int k) {
    dim3 g(n / 128, m / 128), blk(256);
    switch (mode) {
        case 0: sgemm_kernel<0><<<g, blk>>>(A, W, bias, C, m, n, k); break;
        case 1: sgemm_kernel<1><<<g, blk>>>(A, W, bias, C, m, n, k); break;
        case 2: sgemm_kernel<2><<<g, blk>>>(A, W, bias, C, m, n, k); break;
        case 3: sgemm_kernel<3><<<g, blk>>>(A, W, bias, C, m, n, k); break;
    }
}

extern "C" void kernel_launch(void* const* d_in, const int* in_sizes, int n_in,
                              void* d_out, int out_size) {
    const float* x_in  = (const float*)d_in[0];
    const float* Wq    = (const float*)d_in[1];
    const float* bq    = (const float*)d_in[2];
    const float* Wk    = (const float*)d_in[3];
    const float* bk    = (const float*)d_in[4];
    const float* Wv    = (const float*)d_in[5];
    const float* bv    = (const float*)d_in[6];
    const float* Wo    = (const float*)d_in[7];
    const float* bo    = (const float*)d_in[8];
    const float* W1    = (const float*)d_in[9];
    const float* b1    = (const float*)d_in[10];
    const float* W2    = (const float*)d_in[11];
    const float* b2    = (const float*)d_in[12];
    const float* ln1_s = (const float*)d_in[13];
    const float* ln1_b = (const float*)d_in[14];
    const float* ln2_s = (const float*)d_in[15];
    const float* ln2_b = (const float*)d_in[16];
    const float* lnf_s = (const float*)d_in[17];
    const float* lnf_b = (const float*)d_in[18];

    float* x = (float*)d_out;
    float *h, *q, *k, *v, *ffn, *kvb, *ksb;
    cudaGetSymbolAddress((void**)&h,   g_h);
    cudaGetSymbolAddress((void**)&q,   g_q);
    cudaGetSymbolAddress((void**)&k,   g_k);
    cudaGetSymbolAddress((void**)&v,   g_v);
    cudaGetSymbolAddress((void**)&ffn, g_ffn);
    cudaGetSymbolAddress((void**)&kvb, g_kv);
    cudaGetSymbolAddress((void**)&ksb, g_ksum);

    // x = sqrt(D) * x_in + pos_emb
    embed_kernel<<<(size_t)M * D / 1024, 256>>>((const float4*)x_in, (float4*)x);

    for (int l = 0; l < NL; ++l) {
        size_t wo  = (size_t)l * D * D;
        size_t bo_ = (size_t)l * D;
        size_t w1o = (size_t)l * D * F;
        size_t b1o = (size_t)l * F;

        // --- attention block ---
        ln_kernel<<<M, 256>>>(x, ln1_s + bo_, ln1_b + bo_, h);
        gemm_launch(3, h, Wq + wo, bq + bo_, q, M, D, D);   // q = elu(h@Wq+bq)+1
        gemm_launch(3, h, Wk + wo, bk + bo_, k, M, D, D);   // k = elu(h@Wk+bk)+1
        gemm_launch(0, h, Wv + wo, bv + bo_, v, M, D, D);   // v = h@Wv+bv
        kv_kernel<<<B * H, 256>>>(k, v, kvb, ksb);
        attnout_kernel<<<B * H * (T / 64), 128>>>(q, kvb, ksb, h);  // attn -> h
        gemm_launch(2, h, Wo + wo, bo + bo_, x, M, D, D);   // x += attn@Wo+bo

        // --- ffn block ---
        ln_kernel<<<M, 256>>>(x, ln2_s + bo_, ln2_b + bo_, h);
        gemm_launch(1, h, W1 + w1o, b1 + b1o, ffn, M, F, D);   // relu
        gemm_launch(2, ffn, W2 + w1o, b2 + bo_, x, M, D, F);   // residual
    }

    ln_kernel<<<M, 256>>>(x, lnf_s, lnf_b, x);
}

// round 4
// speedup vs baseline: 2.4547x; 2.4547x over previous
#include <cuda_runtime.h>
#include <cuda_bf16.h>
#include <cstdint>

// ---------------------------------------------------------------------------
// Problem constants
// ---------------------------------------------------------------------------
namespace {
constexpr int B  = 8;
constexpr int T  = 2048;
constexpr int D  = 1024;
constexpr int H  = 16;
constexpr int NL = 4;
constexpr int DK = 64;           // D / H
constexpr int M  = B * T;        // 16384 rows
constexpr int F  = 4 * D;        // 4096 ffn hidden
constexpr size_t DD   = (size_t)D * D;
constexpr size_t DF   = (size_t)D * F;
constexpr size_t WBLK = 4 * DD + 2 * DF;   // split-weight block per layer
}

// ---------------------------------------------------------------------------
// Scratch (static device memory — no allocations allowed)
// ---------------------------------------------------------------------------
__device__ __nv_bfloat16 g_hh[(size_t)M * D];    // LN out hi
__device__ __nv_bfloat16 g_hl[(size_t)M * D];    // LN out lo
__device__ __nv_bfloat16 g_oh[(size_t)M * D];    // attn out hi
__device__ __nv_bfloat16 g_ol[(size_t)M * D];    // attn out lo
__device__ __nv_bfloat16 g_fh[(size_t)M * F];    // relu(ffn) hi
__device__ __nv_bfloat16 g_fl[(size_t)M * F];    // relu(ffn) lo
__device__ float g_q[(size_t)M * D];
__device__ float g_k[(size_t)M * D];
__device__ float g_v[(size_t)M * D];
__device__ float g_kv  [B * H * DK * DK];
__device__ float g_ksum[B * H * DK];
__device__ __nv_bfloat16 g_wh[(size_t)NL * WBLK];  // transposed weights [N][K] hi
__device__ __nv_bfloat16 g_wl[(size_t)NL * WBLK];  // transposed weights [N][K] lo

// ---------------------------------------------------------------------------
// Helpers
// ---------------------------------------------------------------------------
__device__ __forceinline__ uint32_t smem_u32(const void* p) {
    uint32_t a;
    asm("{ .reg .u64 t; cvta.to.shared.u64 t, %1; cvt.u32.u64 %0, t; }" : "=r"(a) : "l"(p));
    return a;
}
__device__ __forceinline__ void bf16_split(float x, __nv_bfloat16& hi, __nv_bfloat16& lo) {
    hi = __float2bfloat16(x);
    lo = __float2bfloat16(x - __bfloat162float(hi));
}
__device__ __forceinline__ void ldmx4(uint32_t* r, uint32_t addr) {
    asm volatile("ldmatrix.sync.aligned.m8n8.x4.shared.b16 {%0,%1,%2,%3}, [%4];"
                 : "=r"(r[0]), "=r"(r[1]), "=r"(r[2]), "=r"(r[3]) : "r"(addr));
}
__device__ __forceinline__ void mma16816(float* d, const uint32_t* a, const uint32_t* b) {
    asm volatile(
        "mma.sync.aligned.m16n8k16.row.col.f32.bf16.bf16.f32 "
        "{%0,%1,%2,%3}, {%4,%5,%6,%7}, {%8,%9}, {%0,%1,%2,%3};"
        : "+f"(d[0]), "+f"(d[1]), "+f"(d[2]), "+f"(d[3])
        : "r"(a[0]), "r"(a[1]), "r"(a[2]), "r"(a[3]), "r"(b[0]), "r"(b[1]));
}
#define CP_ASYNC16(dst, src) \
    asm volatile("cp.async.cg.shared.global [%0], [%1], 16;" :: "r"(dst), "l"(src))
#define CP_COMMIT() asm volatile("cp.async.commit_group;" ::: "memory")
#define CP_WAIT2()  asm volatile("cp.async.wait_group 2;" ::: "memory")

// ---------------------------------------------------------------------------
// mma.sync bf16 3-pass GEMM:
//   C[M,N] = op( (Ah+Al)[M,K] @ (Bh+Bl)[N,K]^T + bias )   (drop Al*Bl)
// MODE 0: plain fp32   1: relu -> split bf16 (Ch,Cl)   2: residual add fp32
// MODE 3: elu(x)+1 fp32
// CTA 128x128, BK=32, 4-stage cp.async pipeline, 8 warps (4x2), warp tile 32x64
// ---------------------------------------------------------------------------
namespace {
constexpr int GSTAGES = 4;
constexpr uint32_t ROWB  = 80;                 // 32 bf16 data + 8 pad = 80 bytes
constexpr uint32_t COMP  = 128 * ROWB;         // 10240 B per component tile
constexpr uint32_t STAGE = 4 * COMP;           // 40960 B per stage
constexpr uint32_t GSMEM = GSTAGES * STAGE + 512;  // + bias
}

template <int MODE>
__global__ void __launch_bounds__(256, 1)
mgemm_kernel(const __nv_bfloat16* __restrict__ Ah, const __nv_bfloat16* __restrict__ Al,
             const __nv_bfloat16* __restrict__ Bh, const __nv_bfloat16* __restrict__ Bl,
             const float* __restrict__ bias, float* __restrict__ C,
             __nv_bfloat16* __restrict__ Ch, __nv_bfloat16* __restrict__ Cl,
             int Nn, int Kk) {
    extern __shared__ char smem[];
    uint32_t sb = smem_u32(smem);
    const int tid  = threadIdx.x;
    const int lane = tid & 31, wid = tid >> 5;
    const int bm = blockIdx.y * 128;
    const int bn = blockIdx.x * 128;
    const int wm = (wid & 3) * 32;
    const int wn = (wid >> 2) * 64;
    float* sbias = reinterpret_cast<float*>(smem + GSTAGES * STAGE);
    if (tid < 128) sbias[tid] = bias[bn + tid];

    const int NK = Kk >> 5;

    // stage loader: 4 components x 512 16B-chunks, 8 cp.async per thread
    auto load_stage = [&](int kt, int st) {
        uint32_t sdst = sb + (uint32_t)st * STAGE;
        int k0 = kt * 32;
#pragma unroll
        for (int comp = 0; comp < 4; ++comp) {
            const __nv_bfloat16* g = (comp == 0) ? Ah : (comp == 1) ? Al
                                   : (comp == 2) ? Bh : Bl;
            int rbase = (comp < 2) ? bm : bn;
#pragma unroll
            for (int t2 = 0; t2 < 2; ++t2) {
                int c   = tid + t2 * 256;
                int row = c >> 2, cc = c & 3;
                const __nv_bfloat16* src = g + (size_t)(rbase + row) * Kk + k0 + cc * 8;
                uint32_t dst = sdst + (uint32_t)comp * COMP + (uint32_t)row * ROWB + cc * 16;
                CP_ASYNC16(dst, src);
            }
        }
    };

    load_stage(0, 0); CP_COMMIT();
    load_stage(1, 1); CP_COMMIT();
    load_stage(2, 2); CP_COMMIT();

    float acc[2][8][4] = {};

    // ldmatrix byte offsets within a component (add kk*2 at use)
    uint32_t a_off[2], b_off[4];
#pragma unroll
    for (int i = 0; i < 2; ++i)
        a_off[i] = (uint32_t)((wm + i * 16 + (lane & 15)) * ROWB + ((lane >> 4) * 8) * 2);
#pragma unroll
    for (int p = 0; p < 4; ++p)
        b_off[p] = (uint32_t)((wn + p * 16 + ((lane >> 4) & 1) * 8 + (lane & 7)) * ROWB +
                              (((lane >> 3) & 1) * 8) * 2);

    for (int kt = 0; kt < NK; ++kt) {
        int st = kt & 3;
        CP_WAIT2();
        __syncthreads();
        if (kt + 3 < NK) load_stage(kt + 3, (kt + 3) & 3);
        CP_COMMIT();

        uint32_t sAh = sb + (uint32_t)st * STAGE;
        uint32_t sAl = sAh + COMP;
        uint32_t sBh = sAh + 2 * COMP;
        uint32_t sBl = sAh + 3 * COMP;

#pragma unroll
        for (int kk = 0; kk < 2; ++kk) {
            uint32_t kb = (uint32_t)kk * 32;   // 16 bf16 = 32 bytes
            uint32_t ah[2][4], al[2][4], bh[4][4], bl[4][4];
#pragma unroll
            for (int i = 0; i < 2; ++i) {
                ldmx4(ah[i], sAh + a_off[i] + kb);
                ldmx4(al[i], sAl + a_off[i] + kb);
            }
#pragma unroll
            for (int p = 0; p < 4; ++p) {
                ldmx4(bh[p], sBh + b_off[p] + kb);
                ldmx4(bl[p], sBl + b_off[p] + kb);
            }
#pragma unroll
            for (int i = 0; i < 2; ++i)
#pragma unroll
                for (int p = 0; p < 4; ++p)
#pragma unroll
                    for (int q2 = 0; q2 < 2; ++q2) {
                        float* dacc = acc[i][p * 2 + q2];
                        mma16816(dacc, ah[i], &bh[p][q2 * 2]);
                        mma16816(dacc, al[i], &bh[p][q2 * 2]);
                        mma16816(dacc, ah[i], &bl[p][q2 * 2]);
                    }
        }
    }

    // epilogue
    const int r_ = lane >> 2;
    const int c_ = (lane & 3) * 2;
#pragma unroll
    for (int i = 0; i < 2; ++i) {
#pragma unroll
        for (int j = 0; j < 8; ++j) {
            int lrow = wm + i * 16 + r_;
            int lcol = wn + j * 8 + c_;
            size_t row0 = (size_t)(bm + lrow);
            int col = bn + lcol;
            float b0 = sbias[lcol], b1 = sbias[lcol + 1];
            float v[4];
            v[0] = acc[i][j][0] + b0; v[1] = acc[i][j][1] + b1;
            v[2] = acc[i][j][2] + b0; v[3] = acc[i][j][3] + b1;
            if (MODE == 3) {
#pragma unroll
                for (int s = 0; s < 4; ++s) v[s] = (v[s] > 0.f) ? (v[s] + 1.f) : expf(v[s]);
            }
            if (MODE == 1) {
#pragma unroll
                for (int s = 0; s < 4; ++s) v[s] = fmaxf(v[s], 0.f);
                __nv_bfloat16 h0, l0, h1, l1;
                bf16_split(v[0], h0, l0); bf16_split(v[1], h1, l1);
                *reinterpret_cast<__nv_bfloat162*>(Ch + row0 * Nn + col) = __nv_bfloat162(h0, h1);
                *reinterpret_cast<__nv_bfloat162*>(Cl + row0 * Nn + col) = __nv_bfloat162(l0, l1);
                bf16_split(v[2], h0, l0); bf16_split(v[3], h1, l1);
                *reinterpret_cast<__nv_bfloat162*>(Ch + (row0 + 8) * Nn + col) = __nv_bfloat162(h0, h1);
                *reinterpret_cast<__nv_bfloat162*>(Cl + (row0 + 8) * Nn + col) = __nv_bfloat162(l0, l1);
            } else {
                float* c0 = C + row0 * Nn + col;
                float* c1 = C + (row0 + 8) * Nn + col;
                if (MODE == 2) {
                    float2 e0 = *reinterpret_cast<const float2*>(c0);
                    float2 e1 = *reinterpret_cast<const float2*>(c1);
                    v[0] += e0.x; v[1] += e0.y; v[2] += e1.x; v[3] += e1.y;
                }
                *reinterpret_cast<float2*>(c0) = make_float2(v[0], v[1]);
                *reinterpret_cast<float2*>(c1) = make_float2(v[2], v[3]);
            }
        }
    }
}

// ---------------------------------------------------------------------------
// Weight transpose + split: in fp32 [R][C] -> out bf16 hi/lo [C][R]
// ---------------------------------------------------------------------------
__global__ void transpose_split_kernel(const float* __restrict__ in,
                                       __nv_bfloat16* __restrict__ oh,
                                       __nv_bfloat16* __restrict__ ol, int R, int C) {
    __shared__ float t[32][33];
    int x  = blockIdx.x * 32 + threadIdx.x;
    int y0 = blockIdx.y * 32;
#pragma unroll
    for (int j = 0; j < 32; j += 8)
        t[threadIdx.y + j][threadIdx.x] = in[(size_t)(y0 + threadIdx.y + j) * C + x];
    __syncthreads();
    int ox  = y0 + threadIdx.x;
    int oy0 = blockIdx.x * 32;
#pragma unroll
    for (int j = 0; j < 32; j += 8) {
        float val = t[threadIdx.x][threadIdx.y + j];
        __nv_bfloat16 hi, lo;
        bf16_split(val, hi, lo);
        size_t idx = (size_t)(oy0 + threadIdx.y + j) * R + ox;
        oh[idx] = hi;
        ol[idx] = lo;
    }
}

// ---------------------------------------------------------------------------
// Embed: x = sqrt(D) * x_in + sinusoidal_pos_emb(t, d)
// ---------------------------------------------------------------------------
__global__ void embed_kernel(const float4* __restrict__ xin, float4* __restrict__ out) {
    int i = blockIdx.x * blockDim.x + threadIdx.x;
    int e0 = i * 4;
    int d0 = e0 & (D - 1);
    int t  = (e0 / D) & (T - 1);
    float4 xv = xin[i];
    float pos = (float)(t + 1);
    const float nlf = -9.21034037197618f / 511.0f;
    float xs[4] = {xv.x, xv.y, xv.z, xv.w};
    float os[4];
#pragma unroll
    for (int j = 0; j < 4; ++j) {
        int d = d0 + j;
        float pe;
        if (d < 512) pe = sinf(pos * expf(nlf * (float)d));
        else         pe = cosf(pos * expf(nlf * (float)(d - 512)));
        os[j] = 32.0f * xs[j] + pe;
    }
    out[i] = make_float4(os[0], os[1], os[2], os[3]);
}

// ---------------------------------------------------------------------------
// LayerNorm. SPLIT=1: write bf16 hi/lo; SPLIT=0: write fp32
// ---------------------------------------------------------------------------
template <int SPLIT>
__global__ void ln_kernel(const float* __restrict__ x, const float* __restrict__ sc,
                          const float* __restrict__ bi, float* __restrict__ outf,
                          __nv_bfloat16* __restrict__ oh, __nv_bfloat16* __restrict__ ol) {
    int row = blockIdx.x, tid = threadIdx.x;
    const float4* xr = reinterpret_cast<const float4*>(x + (size_t)row * D);
    float4 v = xr[tid];
    float s = v.x + v.y + v.z + v.w;
    float q = v.x * v.x + v.y * v.y + v.z * v.z + v.w * v.w;
#pragma unroll
    for (int o = 16; o > 0; o >>= 1) {
        s += __shfl_xor_sync(0xffffffffu, s, o);
        q += __shfl_xor_sync(0xffffffffu, q, o);
    }
    __shared__ float ss[8], sq[8];
    if ((tid & 31) == 0) { ss[tid >> 5] = s; sq[tid >> 5] = q; }
    __syncthreads();
    s = 0.f; q = 0.f;
#pragma unroll
    for (int w = 0; w < 8; ++w) { s += ss[w]; q += sq[w]; }
    float mu  = s * (1.0f / D);
    float var = q * (1.0f / D) - mu * mu;
    float rs  = rsqrtf(var + 1e-5f);
    float4 s4 = reinterpret_cast<const float4*>(sc)[tid];
    float4 b4 = reinterpret_cast<const float4*>(bi)[tid];
    float o0 = (v.x - mu) * rs * s4.x + b4.x;
    float o1 = (v.y - mu) * rs * s4.y + b4.y;
    float o2 = (v.z - mu) * rs * s4.z + b4.z;
    float o3 = (v.w - mu) * rs * s4.w + b4.w;
    if (SPLIT) {
        __nv_bfloat16 h0, l0, h1, l1, h2, l2, h3, l3;
        bf16_split(o0, h0, l0); bf16_split(o1, h1, l1);
        bf16_split(o2, h2, l2); bf16_split(o3, h3, l3);
        __nv_bfloat162* ohp = reinterpret_cast<__nv_bfloat162*>(oh + (size_t)row * D);
        __nv_bfloat162* olp = reinterpret_cast<__nv_bfloat162*>(ol + (size_t)row * D);
        ohp[tid * 2]     = __nv_bfloat162(h0, h1);
        ohp[tid * 2 + 1] = __nv_bfloat162(h2, h3);
        olp[tid * 2]     = __nv_bfloat162(l0, l1);
        olp[tid * 2 + 1] = __nv_bfloat162(l2, l3);
    } else {
        reinterpret_cast<float4*>(outf + (size_t)row * D)[tid] = make_float4(o0, o1, o2, o3);
    }
}

// ---------------------------------------------------------------------------
// kv[b,h,m,d] = sum_t kp[.,d] * v[.,m];  ksum[b,h,d] = sum_t kp[.,d]
// ---------------------------------------------------------------------------
__global__ void kv_kernel(const float* __restrict__ kp, const float* __restrict__ vv,
                          float* __restrict__ kv, float* __restrict__ ksum) {
    int bh = blockIdx.x;
    int b = bh / H, h = bh % H;
    __shared__ float ks[32][64];
    __shared__ float vs[32][64];
    int tid = threadIdx.x;
    int tm = (tid / 16) * 4;
    int td = (tid % 16) * 4;
    float acc[4][4] = {};
    float ksacc = 0.f;
    int lr = tid / 8;
    int lc = (tid % 8) * 8;
    size_t base = ((size_t)b * T * H + h) * DK;

    for (int t0 = 0; t0 < T; t0 += 32) {
        const float* kg = kp + base + (size_t)(t0 + lr) * (H * DK) + lc;
        const float* vg = vv + base + (size_t)(t0 + lr) * (H * DK) + lc;
        *reinterpret_cast<float4*>(&ks[lr][lc])     = *reinterpret_cast<const float4*>(kg);
        *reinterpret_cast<float4*>(&ks[lr][lc + 4]) = *reinterpret_cast<const float4*>(kg + 4);
        *reinterpret_cast<float4*>(&vs[lr][lc])     = *reinterpret_cast<const float4*>(vg);
        *reinterpret_cast<float4*>(&vs[lr][lc + 4]) = *reinterpret_cast<const float4*>(vg + 4);
        __syncthreads();
#pragma unroll 8
        for (int t = 0; t < 32; ++t) {
            float4 vm = *reinterpret_cast<const float4*>(&vs[t][tm]);
            float4 kd = *reinterpret_cast<const float4*>(&ks[t][td]);
            float vr[4] = {vm.x, vm.y, vm.z, vm.w};
            float kr[4] = {kd.x, kd.y, kd.z, kd.w};
#pragma unroll
            for (int i = 0; i < 4; ++i)
#pragma unroll
                for (int j = 0; j < 4; ++j)
                    acc[i][j] = fmaf(vr[i], kr[j], acc[i][j]);
        }
        if (tid < 64) {
#pragma unroll 8
            for (int t = 0; t < 32; ++t) ksacc += ks[t][tid];
        }
        __syncthreads();
    }
    float* kvb = kv + (size_t)bh * DK * DK;
#pragma unroll
    for (int i = 0; i < 4; ++i)
        *reinterpret_cast<float4*>(&kvb[(size_t)(tm + i) * DK + td]) =
            make_float4(acc[i][0], acc[i][1], acc[i][2], acc[i][3]);
    if (tid < 64) ksum[bh * DK + tid] = ksacc;
}

// ---------------------------------------------------------------------------
// out[b,t,h,m] = (sum_d qp * kv[m,d]) / (qp . ksum + eps); write split bf16
// ---------------------------------------------------------------------------
__global__ void attnout_kernel(const float* __restrict__ qp, const float* __restrict__ kv,
                               const float* __restrict__ ksum,
                               __nv_bfloat16* __restrict__ oh, __nv_bfloat16* __restrict__ ol) {
    constexpr int NCH = T / 64;
    int id = blockIdx.x;
    int chunk = id % NCH;
    int h = (id / NCH) % H;
    int b = id / (NCH * H);
    __shared__ float kvs[64 * 64];
    __shared__ float qs[64][64];
    __shared__ float kss[64];
    int tid = threadIdx.x;
    const float* kvg = kv + (size_t)(b * H + h) * (DK * DK);
#pragma unroll
    for (int it = 0; it < 8; ++it) {
        int g  = tid + it * 128;
        int m  = g >> 4;
        int d0 = (g & 15) * 4;
        float4 val = reinterpret_cast<const float4*>(kvg)[g];
        kvs[(d0 + 0) * 64 + m] = val.x;
        kvs[(d0 + 1) * 64 + m] = val.y;
        kvs[(d0 + 2) * 64 + m] = val.z;
        kvs[(d0 + 3) * 64 + m] = val.w;
    }
    if (tid < 64) kss[tid] = ksum[(b * H + h) * DK + tid];
    int t0 = chunk * 64;
    size_t qbase = (((size_t)b * T + t0) * H + h) * DK;
    {
        int r = tid >> 1;
        int c = (tid & 1) * 32;
        const float4* qg = reinterpret_cast<const float4*>(qp + qbase + (size_t)r * (H * DK) + c);
        float4* qd = reinterpret_cast<float4*>(&qs[r][c]);
#pragma unroll
        for (int j = 0; j < 8; ++j) qd[j] = qg[j];
    }
    __syncthreads();

    int mm = tid & 63;
    int hf = tid >> 6;
    for (int r = hf; r < 64; r += 2) {
        float o = 0.f, den = 0.f;
#pragma unroll
        for (int d = 0; d < 64; d += 4) {
            float4 q4 = *reinterpret_cast<const float4*>(&qs[r][d]);
            float4 k4 = *reinterpret_cast<const float4*>(&kss[d]);
            den += q4.x * k4.x + q4.y * k4.y + q4.z * k4.z + q4.w * k4.w;
            o = fmaf(q4.x, kvs[(d + 0) * 64 + mm], o);
            o = fmaf(q4.y, kvs[(d + 1) * 64 + mm], o);
            o = fmaf(q4.z, kvs[(d + 2) * 64 + mm], o);
            o = fmaf(q4.w, kvs[(d + 3) * 64 + mm], o);
        }
        float val = o / (den + 1e-6f);
        __nv_bfloat16 hi, lo;
        bf16_split(val, hi, lo);
        size_t oi = qbase + (size_t)r * (H * DK) + mm;
        oh[oi] = hi;
        ol[oi] = lo;
    }
}

// ---------------------------------------------------------------------------
// Host orchestration
// ---------------------------------------------------------------------------
static inline void mgemm(int mode,
                         const __nv_bfloat16* Ah, const __nv_bfloat16* Al,
                         const __nv_bfloat16* Bh, const __nv_bfloat16* Bl,
                         const float* bias, float* C,
                         __nv_bfloat16* Ch, __nv_bfloat16* Cl, int n, int k) {
    dim3 g(n / 128, M / 128), blk(256);
    switch (mode) {
        case 0: mgemm_kernel<0><<<g, blk, GSMEM>>>(Ah, Al, Bh, Bl, bias, C, Ch, Cl, n, k); break;
        case 1: mgemm_kernel<1><<<g, blk, GSMEM>>>(Ah, Al, Bh, Bl, bias, C, Ch, Cl, n, k); break;
        case 2: mgemm_kernel<2><<<g, blk, GSMEM>>>(Ah, Al, Bh, Bl, bias, C, Ch, Cl, n, k); break;
        case 3: mgemm_kernel<3><<<g, blk, GSMEM>>>(Ah, Al, Bh, Bl, bias, C, Ch, Cl, n, k); break;
    }
}

extern "C" void kernel_launch(void* const* d_in, const int* in_sizes, int n_in,
                              void* d_out, int out_size) {
    const float* x_in  = (const float*)d_in[0];
    const float* Wq    = (const float*)d_in[1];
    const float* bq    = (const float*)d_in[2];
    const float* Wk    = (const float*)d_in[3];
    const float* bk    = (const float*)d_in[4];
    const float* Wv    = (const float*)d_in[5];
    const float* bv    = (const float*)d_in[6];
    const float* Wo    = (const float*)d_in[7];
    const float* bo    = (const float*)d_in[8];
    const float* W1    = (const float*)d_in[9];
    const float* b1    = (const float*)d_in[10];
    const float* W2    = (const float*)d_in[11];
    const float* b2    = (const float*)d_in[12];
    const float* ln1_s = (const float*)d_in[13];
    const float* ln1_b = (const float*)d_in[14];
    const float* ln2_s = (const float*)d_in[15];
    const float* ln2_b = (const float*)d_in[16];
    const float* lnf_s = (const float*)d_in[17];
    const float* lnf_b = (const float*)d_in[18];

    cudaFuncSetAttribute(mgemm_kernel<0>, cudaFuncAttributeMaxDynamicSharedMemorySize, GSMEM);
    cudaFuncSetAttribute(mgemm_kernel<1>, cudaFuncAttributeMaxDynamicSharedMemorySize, GSMEM);
    cudaFuncSetAttribute(mgemm_kernel<2>, cudaFuncAttributeMaxDynamicSharedMemorySize, GSMEM);
    cudaFuncSetAttribute(mgemm_kernel<3>, cudaFuncAttributeMaxDynamicSharedMemorySize, GSMEM);

    float* x = (float*)d_out;
    __nv_bfloat16 *hh, *hl, *ohp, *olp, *fh, *fl, *wh, *wl;
    float *q, *k, *v, *kvb, *ksb;
    cudaGetSymbolAddress((void**)&hh,  g_hh);
    cudaGetSymbolAddress((void**)&hl,  g_hl);
    cudaGetSymbolAddress((void**)&ohp, g_oh);
    cudaGetSymbolAddress((void**)&olp, g_ol);
    cudaGetSymbolAddress((void**)&fh,  g_fh);
    cudaGetSymbolAddress((void**)&fl,  g_fl);
    cudaGetSymbolAddress((void**)&q,   g_q);
    cudaGetSymbolAddress((void**)&k,   g_k);
    cudaGetSymbolAddress((void**)&v,   g_v);
    cudaGetSymbolAddress((void**)&kvb, g_kv);
    cudaGetSymbolAddress((void**)&ksb, g_ksum);
    cudaGetSymbolAddress((void**)&wh,  g_wh);
    cudaGetSymbolAddress((void**)&wl,  g_wl);

    // transpose + split all weights to bf16 [N][K]
    dim3 b32(32, 8);
    for (int l = 0; l < NL; ++l) {
        size_t wb = (size_t)l * WBLK;
        size_t wo = (size_t)l * DD, w1 = (size_t)l * DF;
        transpose_split_kernel<<<dim3(D / 32, D / 32), b32>>>(Wq + wo, wh + wb,          wl + wb,          D, D);
        transpose_split_kernel<<<dim3(D / 32, D / 32), b32>>>(Wk + wo, wh + wb + DD,     wl + wb + DD,     D, D);
        transpose_split_kernel<<<dim3(D / 32, D / 32), b32>>>(Wv + wo, wh + wb + 2 * DD, wl + wb + 2 * DD, D, D);
        transpose_split_kernel<<<dim3(D / 32, D / 32), b32>>>(Wo + wo, wh + wb + 3 * DD, wl + wb + 3 * DD, D, D);
        transpose_split_kernel<<<dim3(F / 32, D / 32), b32>>>(W1 + w1, wh + wb + 4 * DD, wl + wb + 4 * DD, D, F);
        transpose_split_kernel<<<dim3(D / 32, F / 32), b32>>>(W2 + w1, wh + wb + 4 * DD + DF, wl + wb + 4 * DD + DF, F, D);
    }

    embed_kernel<<<(size_t)M * D / 1024, 256>>>((const float4*)x_in, (float4*)x);

    for (int l = 0; l < NL; ++l) {
        size_t wb  = (size_t)l * WBLK;
        size_t bo_ = (size_t)l * D;
        size_t b1o = (size_t)l * F;
        const __nv_bfloat16 *wqh = wh + wb,          *wql = wl + wb;
        const __nv_bfloat16 *wkh = wh + wb + DD,     *wkl = wl + wb + DD;
        const __nv_bfloat16 *wvh = wh + wb + 2 * DD, *wvl = wl + wb + 2 * DD;
        const __nv_bfloat16 *woh = wh + wb + 3 * DD, *wol = wl + wb + 3 * DD;
        const __nv_bfloat16 *w1h = wh + wb + 4 * DD, *w1l = wl + wb + 4 * DD;
        const __nv_bfloat16 *w2h = wh + wb + 4 * DD + DF, *w2l = wl + wb + 4 * DD + DF;

        // --- attention block ---
        ln_kernel<1><<<M, 256>>>(x, ln1_s + bo_, ln1_b + bo_, nullptr, hh, hl);
        mgemm(3, hh, hl, wqh, wql, bq + bo_, q, nullptr, nullptr, D, D);  // q = elu+1
        mgemm(3, hh, hl, wkh, wkl, bk + bo_, k, nullptr, nullptr, D, D);  // k = elu+1
        mgemm(0, hh, hl, wvh, wvl, bv + bo_, v, nullptr, nullptr, D, D);  // v
        kv_kernel<<<B * H, 256>>>(k, v, kvb, ksb);
        attnout_kernel<<<B * H * (T / 64), 128>>>(q, kvb, ksb, ohp, olp);
        mgemm(2, ohp, olp, woh, wol, bo + bo_, x, nullptr, nullptr, D, D);  // x += attn@Wo

        // --- ffn block ---
        ln_kernel<1><<<M, 256>>>(x, ln2_s + bo_, ln2_b + bo_, nullptr, hh, hl);
        mgemm(1, hh, hl, w1h, w1l, b1 + b1o, nullptr, fh, fl, F, D);        // relu, split out
        mgemm(2, fh, fl, w2h, w2l, b2 + bo_, x, nullptr, nullptr, D, F);    // x += ffn@W2
    }

    ln_kernel<0><<<M, 256>>>(x, lnf_s, lnf_b, x, nullptr, nullptr);
}

// round 5
// speedup vs baseline: 3.8231x; 1.5575x over previous
#include <cuda_runtime.h>
#include <cuda_fp16.h>
#include <cstdint>

// ---------------------------------------------------------------------------
// Problem constants
// ---------------------------------------------------------------------------
namespace {
constexpr int B  = 8;
constexpr int T  = 2048;
constexpr int D  = 1024;
constexpr int H  = 16;
constexpr int NL = 4;
constexpr int DK = 64;           // D / H
constexpr int M  = B * T;        // 16384 rows
constexpr int F  = 4 * D;        // 4096 ffn hidden
constexpr size_t DD   = (size_t)D * D;
constexpr size_t DF   = (size_t)D * F;
constexpr size_t WBLK = 4 * DD + 2 * DF;   // split-weight block per layer
}

// ---------------------------------------------------------------------------
// Scratch (static device memory — no allocations allowed)
// ---------------------------------------------------------------------------
__device__ __half g_hh[(size_t)M * D];     // LN out (fp16)
__device__ __half g_oh[(size_t)M * D];     // attn out (fp16)
__device__ __half g_fh[(size_t)M * F];     // relu(ffn) (fp16)
__device__ float g_q[(size_t)M * D];
__device__ float g_k[(size_t)M * D];
__device__ float g_v[(size_t)M * D];
__device__ float g_kv  [B * H * DK * DK];
__device__ float g_ksum[B * H * DK];
__device__ float g_pe[(size_t)T * D];      // sinusoidal PE table
__device__ __half g_wh[(size_t)NL * WBLK]; // transposed weights [N][K] hi
__device__ __half g_wl[(size_t)NL * WBLK]; // transposed weights [N][K] lo

// ---------------------------------------------------------------------------
// Helpers
// ---------------------------------------------------------------------------
__device__ __forceinline__ uint32_t smem_u32(const void* p) {
    uint32_t a;
    asm("{ .reg .u64 t; cvta.to.shared.u64 t, %1; cvt.u32.u64 %0, t; }" : "=r"(a) : "l"(p));
    return a;
}
__device__ __forceinline__ void h16_split(float x, __half& hi, __half& lo) {
    hi = __float2half(x);
    lo = __float2half(x - __half2float(hi));
}
__device__ __forceinline__ void ldmx4(uint32_t* r, uint32_t addr) {
    asm volatile("ldmatrix.sync.aligned.m8n8.x4.shared.b16 {%0,%1,%2,%3}, [%4];"
                 : "=r"(r[0]), "=r"(r[1]), "=r"(r[2]), "=r"(r[3]) : "r"(addr));
}
__device__ __forceinline__ void mma16816(float* d, const uint32_t* a, const uint32_t* b) {
    asm volatile(
        "mma.sync.aligned.m16n8k16.row.col.f32.f16.f16.f32 "
        "{%0,%1,%2,%3}, {%4,%5,%6,%7}, {%8,%9}, {%0,%1,%2,%3};"
        : "+f"(d[0]), "+f"(d[1]), "+f"(d[2]), "+f"(d[3])
        : "r"(a[0]), "r"(a[1]), "r"(a[2]), "r"(a[3]), "r"(b[0]), "r"(b[1]));
}
#define CP_ASYNC16(dst, src) \
    asm volatile("cp.async.cg.shared.global [%0], [%1], 16;" :: "r"(dst), "l"(src))
#define CP_COMMIT() asm volatile("cp.async.commit_group;" ::: "memory")
#define CP_WAIT1()  asm volatile("cp.async.wait_group 1;" ::: "memory")

// ---------------------------------------------------------------------------
// mma.sync fp16 2-pass GEMM:
//   C[M,N] = op( A[M,K] @ (Bh+Bl)[N,K]^T + bias )      (A single fp16)
// MODE 0: plain fp32   1: relu -> fp16 Ch   2: residual add fp32   3: elu+1
// CTA 128x128, BK=32, 3-stage cp.async pipeline, 8 warps (4x2), 2 CTAs/SM
// ---------------------------------------------------------------------------
namespace {
constexpr int GSTAGES = 3;
constexpr uint32_t ROWB  = 80;                 // 32 fp16 data + 16B pad
constexpr uint32_t COMP  = 128 * ROWB;         // 10240 B per component tile
constexpr uint32_t STAGE = 3 * COMP;           // A, Bh, Bl = 30720 B
constexpr uint32_t GSMEM = GSTAGES * STAGE + 512;  // + bias ~ 92.7 KB
}

template <int MODE>
__global__ void __launch_bounds__(256, 2)
mgemm_kernel(const __half* __restrict__ A,
             const __half* __restrict__ Bh, const __half* __restrict__ Bl,
             const float* __restrict__ bias, float* __restrict__ C,
             __half* __restrict__ Ch, int Nn, int Kk) {
    extern __shared__ char smem[];
    uint32_t sb = smem_u32(smem);
    const int tid  = threadIdx.x;
    const int lane = tid & 31, wid = tid >> 5;
    const int bm = blockIdx.y * 128;
    const int bn = blockIdx.x * 128;
    const int wm = (wid & 3) * 32;
    const int wn = (wid >> 2) * 64;
    float* sbias = reinterpret_cast<float*>(smem + GSTAGES * STAGE);
    if (tid < 128) sbias[tid] = bias[bn + tid];

    const int NK = Kk >> 5;

    // stage loader: 3 components x 512 16B-chunks, 6 cp.async per thread
    auto load_stage = [&](int kt, int st) {
        uint32_t sdst = sb + (uint32_t)st * STAGE;
        int k0 = kt * 32;
#pragma unroll
        for (int comp = 0; comp < 3; ++comp) {
            const __half* g = (comp == 0) ? A : (comp == 1) ? Bh : Bl;
            int rbase = (comp == 0) ? bm : bn;
#pragma unroll
            for (int t2 = 0; t2 < 2; ++t2) {
                int c   = tid + t2 * 256;
                int row = c >> 2, cc = c & 3;
                const __half* src = g + (size_t)(rbase + row) * Kk + k0 + cc * 8;
                uint32_t dst = sdst + (uint32_t)comp * COMP + (uint32_t)row * ROWB + cc * 16;
                CP_ASYNC16(dst, src);
            }
        }
    };

    load_stage(0, 0); CP_COMMIT();
    load_stage(1, 1); CP_COMMIT();

    float acc[2][8][4] = {};

    // ldmatrix byte offsets within a component (add kk*32 bytes at use)
    uint32_t a_off[2], b_off[4];
#pragma unroll
    for (int i = 0; i < 2; ++i)
        a_off[i] = (uint32_t)((wm + i * 16 + (lane & 15)) * ROWB + ((lane >> 4) * 8) * 2);
#pragma unroll
    for (int p = 0; p < 4; ++p)
        b_off[p] = (uint32_t)((wn + p * 16 + ((lane >> 4) & 1) * 8 + (lane & 7)) * ROWB +
                              (((lane >> 3) & 1) * 8) * 2);

    int st = 0;
    for (int kt = 0; kt < NK; ++kt) {
        CP_WAIT1();
        __syncthreads();
        {
            int ldk = kt + 2;
            if (ldk < NK) {
                int ls = st + 2; if (ls >= 3) ls -= 3;
                load_stage(ldk, ls);
            }
        }
        CP_COMMIT();

        uint32_t sA  = sb + (uint32_t)st * STAGE;
        uint32_t sBh = sA + COMP;
        uint32_t sBl = sA + 2 * COMP;

#pragma unroll
        for (int kk = 0; kk < 2; ++kk) {
            uint32_t kb = (uint32_t)kk * 32;   // 16 fp16 = 32 bytes
            uint32_t ar[2][4], br[4][4];
#pragma unroll
            for (int i = 0; i < 2; ++i) ldmx4(ar[i], sA + a_off[i] + kb);
            // pass 0: A * Bh — 16 independent MMAs
#pragma unroll
            for (int p = 0; p < 4; ++p) ldmx4(br[p], sBh + b_off[p] + kb);
#pragma unroll
            for (int i = 0; i < 2; ++i)
#pragma unroll
                for (int p = 0; p < 4; ++p)
#pragma unroll
                    for (int q2 = 0; q2 < 2; ++q2)
                        mma16816(acc[i][p * 2 + q2], ar[i], &br[p][q2 * 2]);
            // pass 1: A * Bl — 16 independent MMAs
#pragma unroll
            for (int p = 0; p < 4; ++p) ldmx4(br[p], sBl + b_off[p] + kb);
#pragma unroll
            for (int i = 0; i < 2; ++i)
#pragma unroll
                for (int p = 0; p < 4; ++p)
#pragma unroll
                    for (int q2 = 0; q2 < 2; ++q2)
                        mma16816(acc[i][p * 2 + q2], ar[i], &br[p][q2 * 2]);
        }
        if (++st == 3) st = 0;
    }

    // epilogue
    const int r_ = lane >> 2;
    const int c_ = (lane & 3) * 2;
#pragma unroll
    for (int i = 0; i < 2; ++i) {
#pragma unroll
        for (int j = 0; j < 8; ++j) {
            int lrow = wm + i * 16 + r_;
            int lcol = wn + j * 8 + c_;
            size_t row0 = (size_t)(bm + lrow);
            int col = bn + lcol;
            float b0 = sbias[lcol], b1 = sbias[lcol + 1];
            float v[4];
            v[0] = acc[i][j][0] + b0; v[1] = acc[i][j][1] + b1;
            v[2] = acc[i][j][2] + b0; v[3] = acc[i][j][3] + b1;
            if (MODE == 3) {
#pragma unroll
                for (int s = 0; s < 4; ++s) v[s] = (v[s] > 0.f) ? (v[s] + 1.f) : expf(v[s]);
            }
            if (MODE == 1) {
#pragma unroll
                for (int s = 0; s < 4; ++s) v[s] = fmaxf(v[s], 0.f);
                *reinterpret_cast<__half2*>(Ch + row0 * Nn + col)       = __floats2half2_rn(v[0], v[1]);
                *reinterpret_cast<__half2*>(Ch + (row0 + 8) * Nn + col) = __floats2half2_rn(v[2], v[3]);
            } else {
                float* c0 = C + row0 * Nn + col;
                float* c1 = C + (row0 + 8) * Nn + col;
                if (MODE == 2) {
                    float2 e0 = *reinterpret_cast<const float2*>(c0);
                    float2 e1 = *reinterpret_cast<const float2*>(c1);
                    v[0] += e0.x; v[1] += e0.y; v[2] += e1.x; v[3] += e1.y;
                }
                *reinterpret_cast<float2*>(c0) = make_float2(v[0], v[1]);
                *reinterpret_cast<float2*>(c1) = make_float2(v[2], v[3]);
            }
        }
    }
}

// ---------------------------------------------------------------------------
// Weight transpose + split: in fp32 [R][C] -> out fp16 hi/lo [C][R]
// ---------------------------------------------------------------------------
__global__ void transpose_split_kernel(const float* __restrict__ in,
                                       __half* __restrict__ oh,
                                       __half* __restrict__ ol, int R, int C) {
    __shared__ float t[32][33];
    int x  = blockIdx.x * 32 + threadIdx.x;
    int y0 = blockIdx.y * 32;
#pragma unroll
    for (int j = 0; j < 32; j += 8)
        t[threadIdx.y + j][threadIdx.x] = in[(size_t)(y0 + threadIdx.y + j) * C + x];
    __syncthreads();
    int ox  = y0 + threadIdx.x;
    int oy0 = blockIdx.x * 32;
#pragma unroll
    for (int j = 0; j < 32; j += 8) {
        float val = t[threadIdx.x][threadIdx.y + j];
        __half hi, lo;
        h16_split(val, hi, lo);
        size_t idx = (size_t)(oy0 + threadIdx.y + j) * R + ox;
        oh[idx] = hi;
        ol[idx] = lo;
    }
}

// ---------------------------------------------------------------------------
// PE table + embed
// ---------------------------------------------------------------------------
__global__ void pe_kernel(float* __restrict__ pe) {
    int g = blockIdx.x * blockDim.x + threadIdx.x;   // element index into T*D
    int t = g >> 10;               // /D
    int d = g & (D - 1);
    float pos = (float)(t + 1);
    const float nlf = -9.21034037197618f / 511.0f;
    float val;
    if (d < 512) val = sinf(pos * expf(nlf * (float)d));
    else         val = cosf(pos * expf(nlf * (float)(d - 512)));
    pe[g] = val;
}

__global__ void embed_kernel(const float4* __restrict__ xin, const float4* __restrict__ pe,
                             float4* __restrict__ out) {
    int i = blockIdx.x * blockDim.x + threadIdx.x;     // float4 index
    int pi = i & (T * D / 4 - 1);
    float4 xv = xin[i];
    float4 pv = pe[pi];
    out[i] = make_float4(32.0f * xv.x + pv.x, 32.0f * xv.y + pv.y,
                         32.0f * xv.z + pv.z, 32.0f * xv.w + pv.w);
}

// ---------------------------------------------------------------------------
// LayerNorm. OUT16=1: write fp16; else fp32
// ---------------------------------------------------------------------------
template <int OUT16>
__global__ void ln_kernel(const float* __restrict__ x, const float* __restrict__ sc,
                          const float* __restrict__ bi, float* __restrict__ outf,
                          __half* __restrict__ oh) {
    int row = blockIdx.x, tid = threadIdx.x;
    const float4* xr = reinterpret_cast<const float4*>(x + (size_t)row * D);
    float4 v = xr[tid];
    float s = v.x + v.y + v.z + v.w;
    float q = v.x * v.x + v.y * v.y + v.z * v.z + v.w * v.w;
#pragma unroll
    for (int o = 16; o > 0; o >>= 1) {
        s += __shfl_xor_sync(0xffffffffu, s, o);
        q += __shfl_xor_sync(0xffffffffu, q, o);
    }
    __shared__ float ss[8], sq[8];
    if ((tid & 31) == 0) { ss[tid >> 5] = s; sq[tid >> 5] = q; }
    __syncthreads();
    s = 0.f; q = 0.f;
#pragma unroll
    for (int w = 0; w < 8; ++w) { s += ss[w]; q += sq[w]; }
    float mu  = s * (1.0f / D);
    float var = q * (1.0f / D) - mu * mu;
    float rs  = rsqrtf(var + 1e-5f);
    float4 s4 = reinterpret_cast<const float4*>(sc)[tid];
    float4 b4 = reinterpret_cast<const float4*>(bi)[tid];
    float o0 = (v.x - mu) * rs * s4.x + b4.x;
    float o1 = (v.y - mu) * rs * s4.y + b4.y;
    float o2 = (v.z - mu) * rs * s4.z + b4.z;
    float o3 = (v.w - mu) * rs * s4.w + b4.w;
    if (OUT16) {
        __half2* ohp = reinterpret_cast<__half2*>(oh + (size_t)row * D);
        ohp[tid * 2]     = __floats2half2_rn(o0, o1);
        ohp[tid * 2 + 1] = __floats2half2_rn(o2, o3);
    } else {
        reinterpret_cast<float4*>(outf + (size_t)row * D)[tid] = make_float4(o0, o1, o2, o3);
    }
}

// ---------------------------------------------------------------------------
// kv[b,h,m,d] = sum_t kp[.,d] * v[.,m];  ksum[b,h,d] = sum_t kp[.,d]
// ---------------------------------------------------------------------------
__global__ void kv_kernel(const float* __restrict__ kp, const float* __restrict__ vv,
                          float* __restrict__ kv, float* __restrict__ ksum) {
    int bh = blockIdx.x;
    int b = bh / H, h = bh % H;
    __shared__ float ks[32][64];
    __shared__ float vs[32][64];
    int tid = threadIdx.x;
    int tm = (tid / 16) * 4;
    int td = (tid % 16) * 4;
    float acc[4][4] = {};
    float ksacc = 0.f;
    int lr = tid / 8;
    int lc = (tid % 8) * 8;
    size_t base = ((size_t)b * T * H + h) * DK;

    for (int t0 = 0; t0 < T; t0 += 32) {
        const float* kg = kp + base + (size_t)(t0 + lr) * (H * DK) + lc;
        const float* vg = vv + base + (size_t)(t0 + lr) * (H * DK) + lc;
        *reinterpret_cast<float4*>(&ks[lr][lc])     = *reinterpret_cast<const float4*>(kg);
        *reinterpret_cast<float4*>(&ks[lr][lc + 4]) = *reinterpret_cast<const float4*>(kg + 4);
        *reinterpret_cast<float4*>(&vs[lr][lc])     = *reinterpret_cast<const float4*>(vg);
        *reinterpret_cast<float4*>(&vs[lr][lc + 4]) = *reinterpret_cast<const float4*>(vg + 4);
        __syncthreads();
#pragma unroll 8
        for (int t = 0; t < 32; ++t) {
            float4 vm = *reinterpret_cast<const float4*>(&vs[t][tm]);
            float4 kd = *reinterpret_cast<const float4*>(&ks[t][td]);
            float vr[4] = {vm.x, vm.y, vm.z, vm.w};
            float kr[4] = {kd.x, kd.y, kd.z, kd.w};
#pragma unroll
            for (int i = 0; i < 4; ++i)
#pragma unroll
                for (int j = 0; j < 4; ++j)
                    acc[i][j] = fmaf(vr[i], kr[j], acc[i][j]);
        }
        if (tid < 64) {
#pragma unroll 8
            for (int t = 0; t < 32; ++t) ksacc += ks[t][tid];
        }
        __syncthreads();
    }
    float* kvb = kv + (size_t)bh * DK * DK;
#pragma unroll
    for (int i = 0; i < 4; ++i)
        *reinterpret_cast<float4*>(&kvb[(size_t)(tm + i) * DK + td]) =
            make_float4(acc[i][0], acc[i][1], acc[i][2], acc[i][3]);
    if (tid < 64) ksum[bh * DK + tid] = ksacc;
}

// ---------------------------------------------------------------------------
// out[b,t,h,m] = (sum_d qp * kv[m,d]) / (qp . ksum + eps); write fp16
// ---------------------------------------------------------------------------
__global__ void attnout_kernel(const float* __restrict__ qp, const float* __restrict__ kv,
                               const float* __restrict__ ksum, __half* __restrict__ oh) {
    constexpr int NCH = T / 64;
    int id = blockIdx.x;
    int chunk = id % NCH;
    int h = (id / NCH) % H;
    int b = id / (NCH * H);
    __shared__ float kvs[64 * 64];
    __shared__ float qs[64][64];
    __shared__ float kss[64];
    int tid = threadIdx.x;
    const float* kvg = kv + (size_t)(b * H + h) * (DK * DK);
#pragma unroll
    for (int it = 0; it < 8; ++it) {
        int g  = tid + it * 128;
        int m  = g >> 4;
        int d0 = (g & 15) * 4;
        float4 val = reinterpret_cast<const float4*>(kvg)[g];
        kvs[(d0 + 0) * 64 + m] = val.x;
        kvs[(d0 + 1) * 64 + m] = val.y;
        kvs[(d0 + 2) * 64 + m] = val.z;
        kvs[(d0 + 3) * 64 + m] = val.w;
    }
    if (tid < 64) kss[tid] = ksum[(b * H + h) * DK + tid];
    int t0 = chunk * 64;
    size_t qbase = (((size_t)b * T + t0) * H + h) * DK;
    {
        int r = tid >> 1;
        int c = (tid & 1) * 32;
        const float4* qg = reinterpret_cast<const float4*>(qp + qbase + (size_t)r * (H * DK) + c);
        float4* qd = reinterpret_cast<float4*>(&qs[r][c]);
#pragma unroll
        for (int j = 0; j < 8; ++j) qd[j] = qg[j];
    }
    __syncthreads();

    int mm = tid & 63;
    int hf = tid >> 6;
    for (int r = hf; r < 64; r += 2) {
        float o = 0.f, den = 0.f;
#pragma unroll
        for (int d = 0; d < 64; d += 4) {
            float4 q4 = *reinterpret_cast<const float4*>(&qs[r][d]);
            float4 k4 = *reinterpret_cast<const float4*>(&kss[d]);
            den += q4.x * k4.x + q4.y * k4.y + q4.z * k4.z + q4.w * k4.w;
            o = fmaf(q4.x, kvs[(d + 0) * 64 + mm], o);
            o = fmaf(q4.y, kvs[(d + 1) * 64 + mm], o);
            o = fmaf(q4.z, kvs[(d + 2) * 64 + mm], o);
            o = fmaf(q4.w, kvs[(d + 3) * 64 + mm], o);
        }
        oh[qbase + (size_t)r * (H * DK) + mm] = __float2half(o / (den + 1e-6f));
    }
}

// ---------------------------------------------------------------------------
// Host orchestration
// ---------------------------------------------------------------------------
static inline void mgemm(int mode, const __half* A, const __half* Bh, const __half* Bl,
                         const float* bias, float* C, __half* Ch, int n, int k) {
    dim3 g(n / 128, M / 128), blk(256);
    switch (mode) {
        case 0: mgemm_kernel<0><<<g, blk, GSMEM>>>(A, Bh, Bl, bias, C, Ch, n, k); break;
        case 1: mgemm_kernel<1><<<g, blk, GSMEM>>>(A, Bh, Bl, bias, C, Ch, n, k); break;
        case 2: mgemm_kernel<2><<<g, blk, GSMEM>>>(A, Bh, Bl, bias, C, Ch, n, k); break;
        case 3: mgemm_kernel<3><<<g, blk, GSMEM>>>(A, Bh, Bl, bias, C, Ch, n, k); break;
    }
}

extern "C" void kernel_launch(void* const* d_in, const int* in_sizes, int n_in,
                              void* d_out, int out_size) {
    const float* x_in  = (const float*)d_in[0];
    const float* Wq    = (const float*)d_in[1];
    const float* bq    = (const float*)d_in[2];
    const float* Wk    = (const float*)d_in[3];
    const float* bk    = (const float*)d_in[4];
    const float* Wv    = (const float*)d_in[5];
    const float* bv    = (const float*)d_in[6];
    const float* Wo    = (const float*)d_in[7];
    const float* bo    = (const float*)d_in[8];
    const float* W1    = (const float*)d_in[9];
    const float* b1    = (const float*)d_in[10];
    const float* W2    = (const float*)d_in[11];
    const float* b2    = (const float*)d_in[12];
    const float* ln1_s = (const float*)d_in[13];
    const float* ln1_b = (const float*)d_in[14];
    const float* ln2_s = (const float*)d_in[15];
    const float* ln2_b = (const float*)d_in[16];
    const float* lnf_s = (const float*)d_in[17];
    const float* lnf_b = (const float*)d_in[18];

    cudaFuncSetAttribute(mgemm_kernel<0>, cudaFuncAttributeMaxDynamicSharedMemorySize, GSMEM);
    cudaFuncSetAttribute(mgemm_kernel<1>, cudaFuncAttributeMaxDynamicSharedMemorySize, GSMEM);
    cudaFuncSetAttribute(mgemm_kernel<2>, cudaFuncAttributeMaxDynamicSharedMemorySize, GSMEM);
    cudaFuncSetAttribute(mgemm_kernel<3>, cudaFuncAttributeMaxDynamicSharedMemorySize, GSMEM);

    float* x = (float*)d_out;
    __half *hh, *ohp, *fh, *wh, *wl;
    float *q, *k, *v, *kvb, *ksb, *pe;
    cudaGetSymbolAddress((void**)&hh,  g_hh);
    cudaGetSymbolAddress((void**)&ohp, g_oh);
    cudaGetSymbolAddress((void**)&fh,  g_fh);
    cudaGetSymbolAddress((void**)&q,   g_q);
    cudaGetSymbolAddress((void**)&k,   g_k);
    cudaGetSymbolAddress((void**)&v,   g_v);
    cudaGetSymbolAddress((void**)&kvb, g_kv);
    cudaGetSymbolAddress((void**)&ksb, g_ksum);
    cudaGetSymbolAddress((void**)&pe,  g_pe);
    cudaGetSymbolAddress((void**)&wh,  g_wh);
    cudaGetSymbolAddress((void**)&wl,  g_wl);

    // transpose + split all weights to fp16 [N][K]
    dim3 b32(32, 8);
    for (int l = 0; l < NL; ++l) {
        size_t wb = (size_t)l * WBLK;
        size_t wo = (size_t)l * DD, w1 = (size_t)l * DF;
        transpose_split_kernel<<<dim3(D / 32, D / 32), b32>>>(Wq + wo, wh + wb,          wl + wb,          D, D);
        transpose_split_kernel<<<dim3(D / 32, D / 32), b32>>>(Wk + wo, wh + wb + DD,     wl + wb + DD,     D, D);
        transpose_split_kernel<<<dim3(D / 32, D / 32), b32>>>(Wv + wo, wh + wb + 2 * DD, wl + wb + 2 * DD, D, D);
        transpose_split_kernel<<<dim3(D / 32, D / 32), b32>>>(Wo + wo, wh + wb + 3 * DD, wl + wb + 3 * DD, D, D);
        transpose_split_kernel<<<dim3(F / 32, D / 32), b32>>>(W1 + w1, wh + wb + 4 * DD, wl + wb + 4 * DD, D, F);
        transpose_split_kernel<<<dim3(D / 32, F / 32), b32>>>(W2 + w1, wh + wb + 4 * DD + DF, wl + wb + 4 * DD + DF, F, D);
    }

    pe_kernel<<<(T * D) / 256, 256>>>(pe);
    embed_kernel<<<(size_t)M * D / 1024, 256>>>((const float4*)x_in, (const float4*)pe, (float4*)x);

    for (int l = 0; l < NL; ++l) {
        size_t wb  = (size_t)l * WBLK;
        size_t bo_ = (size_t)l * D;
        size_t b1o = (size_t)l * F;
        const __half *wqh = wh + wb,          *wql = wl + wb;
        const __half *wkh = wh + wb + DD,     *wkl = wl + wb + DD;
        const __half *wvh = wh + wb + 2 * DD, *wvl = wl + wb + 2 * DD;
        const __half *woh = wh + wb + 3 * DD, *wol = wl + wb + 3 * DD;
        const __half *w1h = wh + wb + 4 * DD, *w1l = wl + wb + 4 * DD;
        const __half *w2h = wh + wb + 4 * DD + DF, *w2l = wl + wb + 4 * DD + DF;

        // --- attention block ---
        ln_kernel<1><<<M, 256>>>(x, ln1_s + bo_, ln1_b + bo_, nullptr, hh);
        mgemm(3, hh, wqh, wql, bq + bo_, q, nullptr, D, D);   // q = elu+1
        mgemm(3, hh, wkh, wkl, bk + bo_, k, nullptr, D, D);   // k = elu+1
        mgemm(0, hh, wvh, wvl, bv + bo_, v, nullptr, D, D);   // v
        kv_kernel<<<B * H, 256>>>(k, v, kvb, ksb);
        attnout_kernel<<<B * H * (T / 64), 128>>>(q, kvb, ksb, ohp);
        mgemm(2, ohp, woh, wol, bo + bo_, x, nullptr, D, D);  // x += attn@Wo

        // --- ffn block ---
        ln_kernel<1><<<M, 256>>>(x, ln2_s + bo_, ln2_b + bo_, nullptr, hh);
        mgemm(1, hh, w1h, w1l, b1 + b1o, nullptr, fh, F, D);  // relu -> fp16
        mgemm(2, fh, w2h, w2l, b2 + bo_, x, nullptr, D, F);   // x += ffn@W2
    }

    ln_kernel<0><<<M, 256>>>(x, lnf_s, lnf_b, x, nullptr);
}

// round 6
// speedup vs baseline: 5.9748x; 1.5628x over previous
#include <cuda_runtime.h>
#include <cuda_fp16.h>
#include <cstdint>

// ---------------------------------------------------------------------------
// Problem constants
// ---------------------------------------------------------------------------
namespace {
constexpr int B  = 8;
constexpr int T  = 2048;
constexpr int D  = 1024;
constexpr int H  = 16;
constexpr int NL = 4;
constexpr int DK = 64;           // D / H
constexpr int M  = B * T;        // 16384 rows
constexpr int F  = 4 * D;        // 4096 ffn hidden
constexpr size_t DD   = (size_t)D * D;
constexpr size_t DF   = (size_t)D * F;
constexpr size_t WBLK = 4 * DD + 2 * DF;   // weight block per layer
}

// ---------------------------------------------------------------------------
// Scratch (static device memory — no allocations allowed)
// ---------------------------------------------------------------------------
__device__ __half g_hh[(size_t)M * D];     // LN out (fp16)
__device__ __half g_oh[(size_t)M * D];     // attn out (fp16)
__device__ __half g_fh[(size_t)M * F];     // relu(ffn) (fp16)
__device__ float g_q[(size_t)M * D];
__device__ float g_k[(size_t)M * D];
__device__ float g_v[(size_t)M * D];
__device__ float g_kv  [B * H * DK * DK];
__device__ float g_ksum[B * H * DK];
__device__ float g_pe[(size_t)T * D];      // sinusoidal PE table
__device__ __half g_wh[(size_t)NL * WBLK]; // transposed weights [N][K] fp16

// ---------------------------------------------------------------------------
// Helpers
// ---------------------------------------------------------------------------
__device__ __forceinline__ uint32_t smem_u32(const void* p) {
    uint32_t a;
    asm("{ .reg .u64 t; cvta.to.shared.u64 t, %1; cvt.u32.u64 %0, t; }" : "=r"(a) : "l"(p));
    return a;
}
__device__ __forceinline__ void ldmx4(uint32_t* r, uint32_t addr) {
    asm volatile("ldmatrix.sync.aligned.m8n8.x4.shared.b16 {%0,%1,%2,%3}, [%4];"
                 : "=r"(r[0]), "=r"(r[1]), "=r"(r[2]), "=r"(r[3]) : "r"(addr));
}
__device__ __forceinline__ void mma16816(float* d, const uint32_t* a, const uint32_t* b) {
    asm volatile(
        "mma.sync.aligned.m16n8k16.row.col.f32.f16.f16.f32 "
        "{%0,%1,%2,%3}, {%4,%5,%6,%7}, {%8,%9}, {%0,%1,%2,%3};"
        : "+f"(d[0]), "+f"(d[1]), "+f"(d[2]), "+f"(d[3])
        : "r"(a[0]), "r"(a[1]), "r"(a[2]), "r"(a[3]), "r"(b[0]), "r"(b[1]));
}
#define CP_ASYNC16(dst, src) \
    asm volatile("cp.async.cg.shared.global [%0], [%1], 16;" :: "r"(dst), "l"(src))
#define CP_COMMIT() asm volatile("cp.async.commit_group;" ::: "memory")
#define CP_WAIT2()  asm volatile("cp.async.wait_group 2;" ::: "memory")

// ---------------------------------------------------------------------------
// mma.sync fp16 single-pass GEMM:  C[M,N] = op( A[M,K] @ B[N,K]^T + bias )
// MODE 0: plain fp32   1: relu -> fp16 Ch   2: residual add fp32   3: elu+1
// CTA 128x128, BK=32, 4-stage cp.async pipeline, 8 warps (4x2), 2 CTAs/SM
// ---------------------------------------------------------------------------
namespace {
constexpr int GSTAGES = 4;
constexpr uint32_t ROWB  = 80;                 // 32 fp16 data + 16B pad
constexpr uint32_t COMP  = 128 * ROWB;         // 10240 B per component tile
constexpr uint32_t STAGE = 2 * COMP;           // A, B = 20480 B
constexpr uint32_t GSMEM = GSTAGES * STAGE + 512;  // ~82.4 KB
}

template <int MODE>
__global__ void __launch_bounds__(256, 2)
mgemm_kernel(const __half* __restrict__ A, const __half* __restrict__ Bw,
             const float* __restrict__ bias, float* __restrict__ C,
             __half* __restrict__ Ch, int Nn, int Kk) {
    extern __shared__ char smem[];
    uint32_t sb = smem_u32(smem);
    const int tid  = threadIdx.x;
    const int lane = tid & 31, wid = tid >> 5;
    const int bm = blockIdx.y * 128;
    const int bn = blockIdx.x * 128;
    const int wm = (wid & 3) * 32;
    const int wn = (wid >> 2) * 64;
    float* sbias = reinterpret_cast<float*>(smem + GSTAGES * STAGE);
    if (tid < 128) sbias[tid] = bias[bn + tid];

    const int NK = Kk >> 5;

    // stage loader: 2 components x 512 16B-chunks, 4 cp.async per thread
    auto load_stage = [&](int kt, int st) {
        uint32_t sdst = sb + (uint32_t)st * STAGE;
        int k0 = kt * 32;
#pragma unroll
        for (int comp = 0; comp < 2; ++comp) {
            const __half* g = (comp == 0) ? A : Bw;
            int rbase = (comp == 0) ? bm : bn;
#pragma unroll
            for (int t2 = 0; t2 < 2; ++t2) {
                int c   = tid + t2 * 256;
                int row = c >> 2, cc = c & 3;
                const __half* src = g + (size_t)(rbase + row) * Kk + k0 + cc * 8;
                uint32_t dst = sdst + (uint32_t)comp * COMP + (uint32_t)row * ROWB + cc * 16;
                CP_ASYNC16(dst, src);
            }
        }
    };

    load_stage(0, 0); CP_COMMIT();
    load_stage(1, 1); CP_COMMIT();
    load_stage(2, 2); CP_COMMIT();

    float acc[2][8][4] = {};

    // ldmatrix byte offsets within a component (add kk*32 bytes at use)
    uint32_t a_off[2], b_off[4];
#pragma unroll
    for (int i = 0; i < 2; ++i)
        a_off[i] = (uint32_t)((wm + i * 16 + (lane & 15)) * ROWB + ((lane >> 4) * 8) * 2);
#pragma unroll
    for (int p = 0; p < 4; ++p)
        b_off[p] = (uint32_t)((wn + p * 16 + ((lane >> 4) & 1) * 8 + (lane & 7)) * ROWB +
                              (((lane >> 3) & 1) * 8) * 2);

    int st = 0;
    for (int kt = 0; kt < NK; ++kt) {
        CP_WAIT2();
        __syncthreads();
        {
            int ldk = kt + 3;
            if (ldk < NK) {
                int ls = st + 3; if (ls >= GSTAGES) ls -= GSTAGES;
                load_stage(ldk, ls);
            }
        }
        CP_COMMIT();

        uint32_t sA = sb + (uint32_t)st * STAGE;
        uint32_t sB = sA + COMP;

#pragma unroll
        for (int kk = 0; kk < 2; ++kk) {
            uint32_t kb = (uint32_t)kk * 32;   // 16 fp16 = 32 bytes
            uint32_t ar[2][4], br[4][4];
#pragma unroll
            for (int i = 0; i < 2; ++i) ldmx4(ar[i], sA + a_off[i] + kb);
#pragma unroll
            for (int p = 0; p < 4; ++p) ldmx4(br[p], sB + b_off[p] + kb);
#pragma unroll
            for (int i = 0; i < 2; ++i)
#pragma unroll
                for (int p = 0; p < 4; ++p)
#pragma unroll
                    for (int q2 = 0; q2 < 2; ++q2)
                        mma16816(acc[i][p * 2 + q2], ar[i], &br[p][q2 * 2]);
        }
        if (++st == GSTAGES) st = 0;
    }

    // epilogue
    const int r_ = lane >> 2;
    const int c_ = (lane & 3) * 2;
#pragma unroll
    for (int i = 0; i < 2; ++i) {
#pragma unroll
        for (int j = 0; j < 8; ++j) {
            int lrow = wm + i * 16 + r_;
            int lcol = wn + j * 8 + c_;
            size_t row0 = (size_t)(bm + lrow);
            int col = bn + lcol;
            float b0 = sbias[lcol], b1 = sbias[lcol + 1];
            float v[4];
            v[0] = acc[i][j][0] + b0; v[1] = acc[i][j][1] + b1;
            v[2] = acc[i][j][2] + b0; v[3] = acc[i][j][3] + b1;
            if (MODE == 3) {
#pragma unroll
                for (int s = 0; s < 4; ++s) v[s] = (v[s] > 0.f) ? (v[s] + 1.f) : expf(v[s]);
            }
            if (MODE == 1) {
#pragma unroll
                for (int s = 0; s < 4; ++s) v[s] = fmaxf(v[s], 0.f);
                *reinterpret_cast<__half2*>(Ch + row0 * Nn + col)       = __floats2half2_rn(v[0], v[1]);
                *reinterpret_cast<__half2*>(Ch + (row0 + 8) * Nn + col) = __floats2half2_rn(v[2], v[3]);
            } else {
                float* c0 = C + row0 * Nn + col;
                float* c1 = C + (row0 + 8) * Nn + col;
                if (MODE == 2) {
                    float2 e0 = *reinterpret_cast<const float2*>(c0);
                    float2 e1 = *reinterpret_cast<const float2*>(c1);
                    v[0] += e0.x; v[1] += e0.y; v[2] += e1.x; v[3] += e1.y;
                }
                *reinterpret_cast<float2*>(c0) = make_float2(v[0], v[1]);
                *reinterpret_cast<float2*>(c1) = make_float2(v[2], v[3]);
            }
        }
    }
}

// ---------------------------------------------------------------------------
// Weight transpose: in fp32 [R][C] -> out fp16 [C][R]
// ---------------------------------------------------------------------------
__global__ void transpose_h_kernel(const float* __restrict__ in,
                                   __half* __restrict__ oh, int R, int C) {
    __shared__ float t[32][33];
    int x  = blockIdx.x * 32 + threadIdx.x;
    int y0 = blockIdx.y * 32;
#pragma unroll
    for (int j = 0; j < 32; j += 8)
        t[threadIdx.y + j][threadIdx.x] = in[(size_t)(y0 + threadIdx.y + j) * C + x];
    __syncthreads();
    int ox  = y0 + threadIdx.x;
    int oy0 = blockIdx.x * 32;
#pragma unroll
    for (int j = 0; j < 32; j += 8)
        oh[(size_t)(oy0 + threadIdx.y + j) * R + ox] = __float2half(t[threadIdx.x][threadIdx.y + j]);
}

// ---------------------------------------------------------------------------
// PE table + embed
// ---------------------------------------------------------------------------
__global__ void pe_kernel(float* __restrict__ pe) {
    int g = blockIdx.x * blockDim.x + threadIdx.x;
    int t = g >> 10;
    int d = g & (D - 1);
    float pos = (float)(t + 1);
    const float nlf = -9.21034037197618f / 511.0f;
    float val;
    if (d < 512) val = sinf(pos * expf(nlf * (float)d));
    else         val = cosf(pos * expf(nlf * (float)(d - 512)));
    pe[g] = val;
}

__global__ void embed_kernel(const float4* __restrict__ xin, const float4* __restrict__ pe,
                             float4* __restrict__ out) {
    int i = blockIdx.x * blockDim.x + threadIdx.x;
    int pi = i & (T * D / 4 - 1);
    float4 xv = xin[i];
    float4 pv = pe[pi];
    out[i] = make_float4(32.0f * xv.x + pv.x, 32.0f * xv.y + pv.y,
                         32.0f * xv.z + pv.z, 32.0f * xv.w + pv.w);
}

// ---------------------------------------------------------------------------
// LayerNorm. OUT16=1: write fp16; else fp32
// ---------------------------------------------------------------------------
template <int OUT16>
__global__ void ln_kernel(const float* __restrict__ x, const float* __restrict__ sc,
                          const float* __restrict__ bi, float* __restrict__ outf,
                          __half* __restrict__ oh) {
    int row = blockIdx.x, tid = threadIdx.x;
    const float4* xr = reinterpret_cast<const float4*>(x + (size_t)row * D);
    float4 v = xr[tid];
    float s = v.x + v.y + v.z + v.w;
    float q = v.x * v.x + v.y * v.y + v.z * v.z + v.w * v.w;
#pragma unroll
    for (int o = 16; o > 0; o >>= 1) {
        s += __shfl_xor_sync(0xffffffffu, s, o);
        q += __shfl_xor_sync(0xffffffffu, q, o);
    }
    __shared__ float ss[8], sq[8];
    if ((tid & 31) == 0) { ss[tid >> 5] = s; sq[tid >> 5] = q; }
    __syncthreads();
    s = 0.f; q = 0.f;
#pragma unroll
    for (int w = 0; w < 8; ++w) { s += ss[w]; q += sq[w]; }
    float mu  = s * (1.0f / D);
    float var = q * (1.0f / D) - mu * mu;
    float rs  = rsqrtf(var + 1e-5f);
    float4 s4 = reinterpret_cast<const float4*>(sc)[tid];
    float4 b4 = reinterpret_cast<const float4*>(bi)[tid];
    float o0 = (v.x - mu) * rs * s4.x + b4.x;
    float o1 = (v.y - mu) * rs * s4.y + b4.y;
    float o2 = (v.z - mu) * rs * s4.z + b4.z;
    float o3 = (v.w - mu) * rs * s4.w + b4.w;
    if (OUT16) {
        __half2* ohp = reinterpret_cast<__half2*>(oh + (size_t)row * D);
        ohp[tid * 2]     = __floats2half2_rn(o0, o1);
        ohp[tid * 2 + 1] = __floats2half2_rn(o2, o3);
    } else {
        reinterpret_cast<float4*>(outf + (size_t)row * D)[tid] = make_float4(o0, o1, o2, o3);
    }
}

// ---------------------------------------------------------------------------
// kv[b,h,m,d] = sum_t kp[.,d] * v[.,m];  ksum[b,h,d] = sum_t kp[.,d]
// ---------------------------------------------------------------------------
__global__ void kv_kernel(const float* __restrict__ kp, const float* __restrict__ vv,
                          float* __restrict__ kv, float* __restrict__ ksum) {
    int bh = blockIdx.x;
    int b = bh / H, h = bh % H;
    __shared__ float ks[32][64];
    __shared__ float vs[32][64];
    int tid = threadIdx.x;
    int tm = (tid / 16) * 4;
    int td = (tid % 16) * 4;
    float acc[4][4] = {};
    float ksacc = 0.f;
    int lr = tid / 8;
    int lc = (tid % 8) * 8;
    size_t base = ((size_t)b * T * H + h) * DK;

    for (int t0 = 0; t0 < T; t0 += 32) {
        const float* kg = kp + base + (size_t)(t0 + lr) * (H * DK) + lc;
        const float* vg = vv + base + (size_t)(t0 + lr) * (H * DK) + lc;
        *reinterpret_cast<float4*>(&ks[lr][lc])     = *reinterpret_cast<const float4*>(kg);
        *reinterpret_cast<float4*>(&ks[lr][lc + 4]) = *reinterpret_cast<const float4*>(kg + 4);
        *reinterpret_cast<float4*>(&vs[lr][lc])     = *reinterpret_cast<const float4*>(vg);
        *reinterpret_cast<float4*>(&vs[lr][lc + 4]) = *reinterpret_cast<const float4*>(vg + 4);
        __syncthreads();
#pragma unroll 8
        for (int t = 0; t < 32; ++t) {
            float4 vm = *reinterpret_cast<const float4*>(&vs[t][tm]);
            float4 kd = *reinterpret_cast<const float4*>(&ks[t][td]);
            float vr[4] = {vm.x, vm.y, vm.z, vm.w};
            float kr[4] = {kd.x, kd.y, kd.z, kd.w};
#pragma unroll
            for (int i = 0; i < 4; ++i)
#pragma unroll
                for (int j = 0; j < 4; ++j)
                    acc[i][j] = fmaf(vr[i], kr[j], acc[i][j]);
        }
        if (tid < 64) {
#pragma unroll 8
            for (int t = 0; t < 32; ++t) ksacc += ks[t][tid];
        }
        __syncthreads();
    }
    float* kvb = kv + (size_t)bh * DK * DK;
#pragma unroll
    for (int i = 0; i < 4; ++i)
        *reinterpret_cast<float4*>(&kvb[(size_t)(tm + i) * DK + td]) =
            make_float4(acc[i][0], acc[i][1], acc[i][2], acc[i][3]);
    if (tid < 64) ksum[bh * DK + tid] = ksacc;
}

// ---------------------------------------------------------------------------
// out[b,t,h,m] = (sum_d qp * kv[m,d]) / (qp . ksum + eps); write fp16
// ---------------------------------------------------------------------------
__global__ void attnout_kernel(const float* __restrict__ qp, const float* __restrict__ kv,
                               const float* __restrict__ ksum, __half* __restrict__ oh) {
    constexpr int NCH = T / 64;
    int id = blockIdx.x;
    int chunk = id % NCH;
    int h = (id / NCH) % H;
    int b = id / (NCH * H);
    __shared__ float kvs[64 * 64];
    __shared__ float qs[64][64];
    __shared__ float kss[64];
    int tid = threadIdx.x;
    const float* kvg = kv + (size_t)(b * H + h) * (DK * DK);
#pragma unroll
    for (int it = 0; it < 8; ++it) {
        int g  = tid + it * 128;
        int m  = g >> 4;
        int d0 = (g & 15) * 4;
        float4 val = reinterpret_cast<const float4*>(kvg)[g];
        kvs[(d0 + 0) * 64 + m] = val.x;
        kvs[(d0 + 1) * 64 + m] = val.y;
        kvs[(d0 + 2) * 64 + m] = val.z;
        kvs[(d0 + 3) * 64 + m] = val.w;
    }
    if (tid < 64) kss[tid] = ksum[(b * H + h) * DK + tid];
    int t0 = chunk * 64;
    size_t qbase = (((size_t)b * T + t0) * H + h) * DK;
    {
        int r = tid >> 1;
        int c = (tid & 1) * 32;
        const float4* qg = reinterpret_cast<const float4*>(qp + qbase + (size_t)r * (H * DK) + c);
        float4* qd = reinterpret_cast<float4*>(&qs[r][c]);
#pragma unroll
        for (int j = 0; j < 8; ++j) qd[j] = qg[j];
    }
    __syncthreads();

    int mm = tid & 63;
    int hf = tid >> 6;
    for (int r = hf; r < 64; r += 2) {
        float o = 0.f, den = 0.f;
#pragma unroll
        for (int d = 0; d < 64; d += 4) {
            float4 q4 = *reinterpret_cast<const float4*>(&qs[r][d]);
            float4 k4 = *reinterpret_cast<const float4*>(&kss[d]);
            den += q4.x * k4.x + q4.y * k4.y + q4.z * k4.z + q4.w * k4.w;
            o = fmaf(q4.x, kvs[(d + 0) * 64 + mm], o);
            o = fmaf(q4.y, kvs[(d + 1) * 64 + mm], o);
            o = fmaf(q4.z, kvs[(d + 2) * 64 + mm], o);
            o = fmaf(q4.w, kvs[(d + 3) * 64 + mm], o);
        }
        oh[qbase + (size_t)r * (H * DK) + mm] = __float2half(o / (den + 1e-6f));
    }
}

// ---------------------------------------------------------------------------
// Host orchestration
// ---------------------------------------------------------------------------
static inline void mgemm(int mode, const __half* A, const __half* Bw,
                         const float* bias, float* C, __half* Ch, int n, int k) {
    dim3 g(n / 128, M / 128), blk(256);
    switch (mode) {
        case 0: mgemm_kernel<0><<<g, blk, GSMEM>>>(A, Bw, bias, C, Ch, n, k); break;
        case 1: mgemm_kernel<1><<<g, blk, GSMEM>>>(A, Bw, bias, C, Ch, n, k); break;
        case 2: mgemm_kernel<2><<<g, blk, GSMEM>>>(A, Bw, bias, C, Ch, n, k); break;
        case 3: mgemm_kernel<3><<<g, blk, GSMEM>>>(A, Bw, bias, C, Ch, n, k); break;
    }
}

extern "C" void kernel_launch(void* const* d_in, const int* in_sizes, int n_in,
                              void* d_out, int out_size) {
    const float* x_in  = (const float*)d_in[0];
    const float* Wq    = (const float*)d_in[1];
    const float* bq    = (const float*)d_in[2];
    const float* Wk    = (const float*)d_in[3];
    const float* bk    = (const float*)d_in[4];
    const float* Wv    = (const float*)d_in[5];
    const float* bv    = (const float*)d_in[6];
    const float* Wo    = (const float*)d_in[7];
    const float* bo    = (const float*)d_in[8];
    const float* W1    = (const float*)d_in[9];
    const float* b1    = (const float*)d_in[10];
    const float* W2    = (const float*)d_in[11];
    const float* b2    = (const float*)d_in[12];
    const float* ln1_s = (const float*)d_in[13];
    const float* ln1_b = (const float*)d_in[14];
    const float* ln2_s = (const float*)d_in[15];
    const float* ln2_b = (const float*)d_in[16];
    const float* lnf_s = (const float*)d_in[17];
    const float* lnf_b = (const float*)d_in[18];

    cudaFuncSetAttribute(mgemm_kernel<0>, cudaFuncAttributeMaxDynamicSharedMemorySize, GSMEM);
    cudaFuncSetAttribute(mgemm_kernel<1>, cudaFuncAttributeMaxDynamicSharedMemorySize, GSMEM);
    cudaFuncSetAttribute(mgemm_kernel<2>, cudaFuncAttributeMaxDynamicSharedMemorySize, GSMEM);
    cudaFuncSetAttribute(mgemm_kernel<3>, cudaFuncAttributeMaxDynamicSharedMemorySize, GSMEM);

    float* x = (float*)d_out;
    __half *hh, *ohp, *fh, *wh;
    float *q, *k, *v, *kvb, *ksb, *pe;
    cudaGetSymbolAddress((void**)&hh,  g_hh);
    cudaGetSymbolAddress((void**)&ohp, g_oh);
    cudaGetSymbolAddress((void**)&fh,  g_fh);
    cudaGetSymbolAddress((void**)&q,   g_q);
    cudaGetSymbolAddress((void**)&k,   g_k);
    cudaGetSymbolAddress((void**)&v,   g_v);
    cudaGetSymbolAddress((void**)&kvb, g_kv);
    cudaGetSymbolAddress((void**)&ksb, g_ksum);
    cudaGetSymbolAddress((void**)&pe,  g_pe);
    cudaGetSymbolAddress((void**)&wh,  g_wh);

    // transpose all weights to fp16 [N][K]
    dim3 b32(32, 8);
    for (int l = 0; l < NL; ++l) {
        size_t wb = (size_t)l * WBLK;
        size_t wo = (size_t)l * DD, w1 = (size_t)l * DF;
        transpose_h_kernel<<<dim3(D / 32, D / 32), b32>>>(Wq + wo, wh + wb,          D, D);
        transpose_h_kernel<<<dim3(D / 32, D / 32), b32>>>(Wk + wo, wh + wb + DD,     D, D);
        transpose_h_kernel<<<dim3(D / 32, D / 32), b32>>>(Wv + wo, wh + wb + 2 * DD, D, D);
        transpose_h_kernel<<<dim3(D / 32, D / 32), b32>>>(Wo + wo, wh + wb + 3 * DD, D, D);
        transpose_h_kernel<<<dim3(F / 32, D / 32), b32>>>(W1 + w1, wh + wb + 4 * DD, D, F);
        transpose_h_kernel<<<dim3(D / 32, F / 32), b32>>>(W2 + w1, wh + wb + 4 * DD + DF, F, D);
    }

    pe_kernel<<<(T * D) / 256, 256>>>(pe);
    embed_kernel<<<(size_t)M * D / 1024, 256>>>((const float4*)x_in, (const float4*)pe, (float4*)x);

    for (int l = 0; l < NL; ++l) {
        size_t wb  = (size_t)l * WBLK;
        size_t bo_ = (size_t)l * D;
        size_t b1o = (size_t)l * F;
        const __half *wq = wh + wb;
        const __half *wk = wh + wb + DD;
        const __half *wv = wh + wb + 2 * DD;
        const __half *wo_ = wh + wb + 3 * DD;
        const __half *w1 = wh + wb + 4 * DD;
        const __half *w2 = wh + wb + 4 * DD + DF;

        // --- attention block ---
        ln_kernel<1><<<M, 256>>>(x, ln1_s + bo_, ln1_b + bo_, nullptr, hh);
        mgemm(3, hh, wq, bq + bo_, q, nullptr, D, D);   // q = elu+1
        mgemm(3, hh, wk, bk + bo_, k, nullptr, D, D);   // k = elu+1
        mgemm(0, hh, wv, bv + bo_, v, nullptr, D, D);   // v
        kv_kernel<<<B * H, 256>>>(k, v, kvb, ksb);
        attnout_kernel<<<B * H * (T / 64), 128>>>(q, kvb, ksb, ohp);
        mgemm(2, ohp, wo_, bo + bo_, x, nullptr, D, D); // x += attn@Wo

        // --- ffn block ---
        ln_kernel<1><<<M, 256>>>(x, ln2_s + bo_, ln2_b + bo_, nullptr, hh);
        mgemm(1, hh, w1, b1 + b1o, nullptr, fh, F, D);  // relu -> fp16
        mgemm(2, fh, w2, b2 + bo_, x, nullptr, D, F);   // x += ffn@W2
    }

    ln_kernel<0><<<M, 256>>>(x, lnf_s, lnf_b, x, nullptr);
}

// round 7
// speedup vs baseline: 6.2996x; 1.0544x over previous
#include <cuda_runtime.h>
#include <cuda_fp16.h>
#include <cstdint>

// ---------------------------------------------------------------------------
// Problem constants
// ---------------------------------------------------------------------------
namespace {
constexpr int B  = 8;
constexpr int T  = 2048;
constexpr int D  = 1024;
constexpr int H  = 16;
constexpr int NL = 4;
constexpr int DK = 64;           // D / H
constexpr int M  = B * T;        // 16384 rows
constexpr int F  = 4 * D;        // 4096 ffn hidden
constexpr int NSPL = 8;          // kv T-splits
constexpr size_t DD   = (size_t)D * D;
constexpr size_t DF   = (size_t)D * F;
constexpr size_t WBLK = 4 * DD + 2 * DF;   // weight block per layer
}

// ---------------------------------------------------------------------------
// Scratch (static device memory — no allocations allowed)
// ---------------------------------------------------------------------------
__device__ __half g_hh[(size_t)M * D];     // LN out (fp16)
__device__ __half g_oh[(size_t)M * D];     // attn out (fp16)
__device__ __half g_fh[(size_t)M * F];     // relu(ffn) (fp16)
__device__ __half g_q[(size_t)M * D];
__device__ __half g_k[(size_t)M * D];
__device__ __half g_v[(size_t)M * D];
__device__ float g_kvp [B * H * NSPL * DK * DK];   // kv partials
__device__ float g_ksp [B * H * NSPL * DK];        // ksum partials
__device__ float g_kv  [B * H * DK * DK];
__device__ float g_ksum[B * H * DK];
__device__ float g_pe[(size_t)T * D];      // sinusoidal PE table
__device__ __half g_wh[(size_t)NL * WBLK]; // transposed weights [N][K] fp16

// ---------------------------------------------------------------------------
// Helpers
// ---------------------------------------------------------------------------
__device__ __forceinline__ uint32_t smem_u32(const void* p) {
    uint32_t a;
    asm("{ .reg .u64 t; cvta.to.shared.u64 t, %1; cvt.u32.u64 %0, t; }" : "=r"(a) : "l"(p));
    return a;
}
__device__ __forceinline__ void ldmx4(uint32_t* r, uint32_t addr) {
    asm volatile("ldmatrix.sync.aligned.m8n8.x4.shared.b16 {%0,%1,%2,%3}, [%4];"
                 : "=r"(r[0]), "=r"(r[1]), "=r"(r[2]), "=r"(r[3]) : "r"(addr));
}
__device__ __forceinline__ void mma16816(float* d, const uint32_t* a, const uint32_t* b) {
    asm volatile(
        "mma.sync.aligned.m16n8k16.row.col.f32.f16.f16.f32 "
        "{%0,%1,%2,%3}, {%4,%5,%6,%7}, {%8,%9}, {%0,%1,%2,%3};"
        : "+f"(d[0]), "+f"(d[1]), "+f"(d[2]), "+f"(d[3])
        : "r"(a[0]), "r"(a[1]), "r"(a[2]), "r"(a[3]), "r"(b[0]), "r"(b[1]));
}
#define CP_ASYNC16(dst, src) \
    asm volatile("cp.async.cg.shared.global [%0], [%1], 16;" :: "r"(dst), "l"(src))
#define CP_COMMIT() asm volatile("cp.async.commit_group;" ::: "memory")
#define CP_WAIT2()  asm volatile("cp.async.wait_group 2;" ::: "memory")

__device__ __forceinline__ void h8_to_f(const uint4& u, float* f) {
    const __half2* h2 = reinterpret_cast<const __half2*>(&u);
#pragma unroll
    for (int i = 0; i < 4; ++i) {
        float2 t = __half22float2(h2[i]);
        f[i * 2] = t.x; f[i * 2 + 1] = t.y;
    }
}

// ---------------------------------------------------------------------------
// mma.sync fp16 single-pass GEMM:  out = op( A[M,K] @ B[N,K]^T + bias )
// MODE 0: plain -> fp16   1: relu -> fp16   2: residual add -> fp32   3: elu+1 -> fp16
// CTA 128x128, BK=32, 4-stage cp.async pipeline, 8 warps (4x2), 2 CTAs/SM
// ---------------------------------------------------------------------------
namespace {
constexpr int GSTAGES = 4;
constexpr uint32_t ROWB  = 80;                 // 32 fp16 data + 16B pad
constexpr uint32_t COMP  = 128 * ROWB;         // 10240 B per component tile
constexpr uint32_t STAGE = 2 * COMP;           // A, B = 20480 B
constexpr uint32_t GSMEM = GSTAGES * STAGE + 512;  // ~82.4 KB
}

template <int MODE>
__global__ void __launch_bounds__(256, 2)
mgemm_kernel(const __half* __restrict__ A, const __half* __restrict__ Bw,
             const float* __restrict__ bias, float* __restrict__ C,
             __half* __restrict__ Ch, int Nn, int Kk) {
    extern __shared__ char smem[];
    uint32_t sb = smem_u32(smem);
    const int tid  = threadIdx.x;
    const int lane = tid & 31, wid = tid >> 5;
    const int bm = blockIdx.y * 128;
    const int bn = blockIdx.x * 128;
    const int wm = (wid & 3) * 32;
    const int wn = (wid >> 2) * 64;
    float* sbias = reinterpret_cast<float*>(smem + GSTAGES * STAGE);
    if (tid < 128) sbias[tid] = bias[bn + tid];

    const int NK = Kk >> 5;

    auto load_stage = [&](int kt, int st) {
        uint32_t sdst = sb + (uint32_t)st * STAGE;
        int k0 = kt * 32;
#pragma unroll
        for (int comp = 0; comp < 2; ++comp) {
            const __half* g = (comp == 0) ? A : Bw;
            int rbase = (comp == 0) ? bm : bn;
#pragma unroll
            for (int t2 = 0; t2 < 2; ++t2) {
                int c   = tid + t2 * 256;
                int row = c >> 2, cc = c & 3;
                const __half* src = g + (size_t)(rbase + row) * Kk + k0 + cc * 8;
                uint32_t dst = sdst + (uint32_t)comp * COMP + (uint32_t)row * ROWB + cc * 16;
                CP_ASYNC16(dst, src);
            }
        }
    };

    load_stage(0, 0); CP_COMMIT();
    load_stage(1, 1); CP_COMMIT();
    load_stage(2, 2); CP_COMMIT();

    float acc[2][8][4] = {};

    uint32_t a_off[2], b_off[4];
#pragma unroll
    for (int i = 0; i < 2; ++i)
        a_off[i] = (uint32_t)((wm + i * 16 + (lane & 15)) * ROWB + ((lane >> 4) * 8) * 2);
#pragma unroll
    for (int p = 0; p < 4; ++p)
        b_off[p] = (uint32_t)((wn + p * 16 + ((lane >> 4) & 1) * 8 + (lane & 7)) * ROWB +
                              (((lane >> 3) & 1) * 8) * 2);

    int st = 0;
    for (int kt = 0; kt < NK; ++kt) {
        CP_WAIT2();
        __syncthreads();
        {
            int ldk = kt + 3;
            if (ldk < NK) {
                int ls = st + 3; if (ls >= GSTAGES) ls -= GSTAGES;
                load_stage(ldk, ls);
            }
        }
        CP_COMMIT();

        uint32_t sA = sb + (uint32_t)st * STAGE;
        uint32_t sB = sA + COMP;

#pragma unroll
        for (int kk = 0; kk < 2; ++kk) {
            uint32_t kb = (uint32_t)kk * 32;
            uint32_t ar[2][4], br[4][4];
#pragma unroll
            for (int i = 0; i < 2; ++i) ldmx4(ar[i], sA + a_off[i] + kb);
#pragma unroll
            for (int p = 0; p < 4; ++p) ldmx4(br[p], sB + b_off[p] + kb);
#pragma unroll
            for (int i = 0; i < 2; ++i)
#pragma unroll
                for (int p = 0; p < 4; ++p)
#pragma unroll
                    for (int q2 = 0; q2 < 2; ++q2)
                        mma16816(acc[i][p * 2 + q2], ar[i], &br[p][q2 * 2]);
        }
        if (++st == GSTAGES) st = 0;
    }

    // epilogue
    const int r_ = lane >> 2;
    const int c_ = (lane & 3) * 2;
#pragma unroll
    for (int i = 0; i < 2; ++i) {
#pragma unroll
        for (int j = 0; j < 8; ++j) {
            int lrow = wm + i * 16 + r_;
            int lcol = wn + j * 8 + c_;
            size_t row0 = (size_t)(bm + lrow);
            int col = bn + lcol;
            float b0 = sbias[lcol], b1 = sbias[lcol + 1];
            float v[4];
            v[0] = acc[i][j][0] + b0; v[1] = acc[i][j][1] + b1;
            v[2] = acc[i][j][2] + b0; v[3] = acc[i][j][3] + b1;
            if (MODE == 3) {
#pragma unroll
                for (int s = 0; s < 4; ++s) v[s] = (v[s] > 0.f) ? (v[s] + 1.f) : expf(v[s]);
            } else if (MODE == 1) {
#pragma unroll
                for (int s = 0; s < 4; ++s) v[s] = fmaxf(v[s], 0.f);
            }
            if (MODE == 2) {
                float* c0 = C + row0 * Nn + col;
                float* c1 = C + (row0 + 8) * Nn + col;
                float2 e0 = *reinterpret_cast<const float2*>(c0);
                float2 e1 = *reinterpret_cast<const float2*>(c1);
                v[0] += e0.x; v[1] += e0.y; v[2] += e1.x; v[3] += e1.y;
                *reinterpret_cast<float2*>(c0) = make_float2(v[0], v[1]);
                *reinterpret_cast<float2*>(c1) = make_float2(v[2], v[3]);
            } else {
                *reinterpret_cast<__half2*>(Ch + row0 * Nn + col)       = __floats2half2_rn(v[0], v[1]);
                *reinterpret_cast<__half2*>(Ch + (row0 + 8) * Nn + col) = __floats2half2_rn(v[2], v[3]);
            }
        }
    }
}

// ---------------------------------------------------------------------------
// Batched weight transpose: all 24 matrices in ONE launch.
// fp32 in[R][C] -> fp16 out[C][R], 32x32 tiles, block (32,8)
// ---------------------------------------------------------------------------
__global__ void transpose_all_kernel(const float* __restrict__ Wq, const float* __restrict__ Wk,
                                     const float* __restrict__ Wv, const float* __restrict__ Wo,
                                     const float* __restrict__ W1, const float* __restrict__ W2,
                                     __half* __restrict__ wh) {
    int idx = blockIdx.x;
    int layer = idx / 12288;
    int rem   = idx % 12288;
    const float* in; __half* out; int R, C, tile;
    size_t wb = (size_t)layer * WBLK;
    if (rem < 4096) {
        int mat = rem >> 10; tile = rem & 1023;
        R = D; C = D;
        in  = (mat == 0 ? Wq : mat == 1 ? Wk : mat == 2 ? Wv : Wo) + (size_t)layer * DD;
        out = wh + wb + (size_t)mat * DD;
    } else if (rem < 8192) {
        tile = rem - 4096; R = D; C = F;
        in  = W1 + (size_t)layer * DF;
        out = wh + wb + 4 * DD;
    } else {
        tile = rem - 8192; R = F; C = D;
        in  = W2 + (size_t)layer * DF;
        out = wh + wb + 4 * DD + DF;
    }
    int gx = C >> 5;
    int bx = tile % gx, by = tile / gx;
    __shared__ float t[32][33];
    int x  = bx * 32 + threadIdx.x;
    int y0 = by * 32;
#pragma unroll
    for (int j = 0; j < 32; j += 8)
        t[threadIdx.y + j][threadIdx.x] = in[(size_t)(y0 + threadIdx.y + j) * C + x];
    __syncthreads();
    int ox  = y0 + threadIdx.x;
    int oy0 = bx * 32;
#pragma unroll
    for (int j = 0; j < 32; j += 8)
        out[(size_t)(oy0 + threadIdx.y + j) * R + ox] = __float2half(t[threadIdx.x][threadIdx.y + j]);
}

// ---------------------------------------------------------------------------
// PE table + embed
// ---------------------------------------------------------------------------
__global__ void pe_kernel(float* __restrict__ pe) {
    int g = blockIdx.x * blockDim.x + threadIdx.x;
    int t = g >> 10;
    int d = g & (D - 1);
    float pos = (float)(t + 1);
    const float nlf = -9.21034037197618f / 511.0f;
    float val;
    if (d < 512) val = sinf(pos * expf(nlf * (float)d));
    else         val = cosf(pos * expf(nlf * (float)(d - 512)));
    pe[g] = val;
}

__global__ void embed_kernel(const float4* __restrict__ xin, const float4* __restrict__ pe,
                             float4* __restrict__ out) {
    int i = blockIdx.x * blockDim.x + threadIdx.x;
    int pi = i & (T * D / 4 - 1);
    float4 xv = xin[i];
    float4 pv = pe[pi];
    out[i] = make_float4(32.0f * xv.x + pv.x, 32.0f * xv.y + pv.y,
                         32.0f * xv.z + pv.z, 32.0f * xv.w + pv.w);
}

// ---------------------------------------------------------------------------
// LayerNorm. OUT16=1: write fp16; else fp32
// ---------------------------------------------------------------------------
template <int OUT16>
__global__ void ln_kernel(const float* __restrict__ x, const float* __restrict__ sc,
                          const float* __restrict__ bi, float* __restrict__ outf,
                          __half* __restrict__ oh) {
    int row = blockIdx.x, tid = threadIdx.x;
    const float4* xr = reinterpret_cast<const float4*>(x + (size_t)row * D);
    float4 v = xr[tid];
    float s = v.x + v.y + v.z + v.w;
    float q = v.x * v.x + v.y * v.y + v.z * v.z + v.w * v.w;
#pragma unroll
    for (int o = 16; o > 0; o >>= 1) {
        s += __shfl_xor_sync(0xffffffffu, s, o);
        q += __shfl_xor_sync(0xffffffffu, q, o);
    }
    __shared__ float ss[8], sq[8];
    if ((tid & 31) == 0) { ss[tid >> 5] = s; sq[tid >> 5] = q; }
    __syncthreads();
    s = 0.f; q = 0.f;
#pragma unroll
    for (int w = 0; w < 8; ++w) { s += ss[w]; q += sq[w]; }
    float mu  = s * (1.0f / D);
    float var = q * (1.0f / D) - mu * mu;
    float rs  = rsqrtf(var + 1e-5f);
    float4 s4 = reinterpret_cast<const float4*>(sc)[tid];
    float4 b4 = reinterpret_cast<const float4*>(bi)[tid];
    float o0 = (v.x - mu) * rs * s4.x + b4.x;
    float o1 = (v.y - mu) * rs * s4.y + b4.y;
    float o2 = (v.z - mu) * rs * s4.z + b4.z;
    float o3 = (v.w - mu) * rs * s4.w + b4.w;
    if (OUT16) {
        __half2* ohp = reinterpret_cast<__half2*>(oh + (size_t)row * D);
        ohp[tid * 2]     = __floats2half2_rn(o0, o1);
        ohp[tid * 2 + 1] = __floats2half2_rn(o2, o3);
    } else {
        reinterpret_cast<float4*>(outf + (size_t)row * D)[tid] = make_float4(o0, o1, o2, o3);
    }
}

// ---------------------------------------------------------------------------
// kv partial: slice s of T. kvp[g][m][d] = sum_t kp[.,d]*v[.,m] over slice
// grid = B*H*NSPL, block 256
// ---------------------------------------------------------------------------
__global__ void kv_kernel(const __half* __restrict__ kp, const __half* __restrict__ vv,
                          float* __restrict__ kvp, float* __restrict__ ksp) {
    int g = blockIdx.x;
    int bh = g >> 3, slice = g & 7;
    int b = bh / H, h = bh % H;
    __shared__ float ks[32][64];
    __shared__ float vs[32][64];
    int tid = threadIdx.x;
    int tm = (tid / 16) * 4;
    int td = (tid % 16) * 4;
    float acc[4][4] = {};
    float ksacc = 0.f;
    int lr = tid / 8;
    int lc = (tid % 8) * 8;
    size_t base = ((size_t)b * T * H + h) * DK;
    int tbeg = slice * (T / NSPL), tend = tbeg + (T / NSPL);

    for (int t0 = tbeg; t0 < tend; t0 += 32) {
        uint4 ku = *reinterpret_cast<const uint4*>(kp + base + (size_t)(t0 + lr) * (H * DK) + lc);
        uint4 vu = *reinterpret_cast<const uint4*>(vv + base + (size_t)(t0 + lr) * (H * DK) + lc);
        h8_to_f(ku, &ks[lr][lc]);
        h8_to_f(vu, &vs[lr][lc]);
        __syncthreads();
#pragma unroll 8
        for (int t = 0; t < 32; ++t) {
            float4 vm = *reinterpret_cast<const float4*>(&vs[t][tm]);
            float4 kd = *reinterpret_cast<const float4*>(&ks[t][td]);
            float vr[4] = {vm.x, vm.y, vm.z, vm.w};
            float kr[4] = {kd.x, kd.y, kd.z, kd.w};
#pragma unroll
            for (int i = 0; i < 4; ++i)
#pragma unroll
                for (int j = 0; j < 4; ++j)
                    acc[i][j] = fmaf(vr[i], kr[j], acc[i][j]);
        }
        if (tid < 64) {
#pragma unroll 8
            for (int t = 0; t < 32; ++t) ksacc += ks[t][tid];
        }
        __syncthreads();
    }
    float* kvb = kvp + (size_t)g * DK * DK;
#pragma unroll
    for (int i = 0; i < 4; ++i)
        *reinterpret_cast<float4*>(&kvb[(size_t)(tm + i) * DK + td]) =
            make_float4(acc[i][0], acc[i][1], acc[i][2], acc[i][3]);
    if (tid < 64) ksp[g * DK + tid] = ksacc;
}

// reduce partials: kv = sum_s kvp, ksum = sum_s ksp
__global__ void kvreduce_kernel(const float* __restrict__ kvp, const float* __restrict__ ksp,
                                float* __restrict__ kv, float* __restrict__ ksum) {
    int i = blockIdx.x * 256 + threadIdx.x;      // over B*H*DK*DK
    int bh = i / (DK * DK);
    int e  = i % (DK * DK);
    float s = 0.f;
#pragma unroll
    for (int s8 = 0; s8 < NSPL; ++s8)
        s += kvp[((size_t)(bh * NSPL + s8)) * (DK * DK) + e];
    kv[i] = s;
    if (i < B * H * DK) {
        int bh2 = i / DK, d = i % DK;
        float t = 0.f;
#pragma unroll
        for (int s8 = 0; s8 < NSPL; ++s8)
            t += ksp[(bh2 * NSPL + s8) * DK + d];
        ksum[i] = t;
    }
}

// ---------------------------------------------------------------------------
// out[b,t,h,m] = (sum_d qp * kv[m,d]) / (qp . ksum + eps); q fp16 in, fp16 out
// ---------------------------------------------------------------------------
__global__ void attnout_kernel(const __half* __restrict__ qp, const float* __restrict__ kv,
                               const float* __restrict__ ksum, __half* __restrict__ oh) {
    constexpr int NCH = T / 64;
    int id = blockIdx.x;
    int chunk = id % NCH;
    int h = (id / NCH) % H;
    int b = id / (NCH * H);
    __shared__ float kvs[64 * 64];
    __shared__ float qs[64][64];
    __shared__ float kss[64];
    int tid = threadIdx.x;
    const float* kvg = kv + (size_t)(b * H + h) * (DK * DK);
#pragma unroll
    for (int it = 0; it < 8; ++it) {
        int g  = tid + it * 128;
        int m  = g >> 4;
        int d0 = (g & 15) * 4;
        float4 val = reinterpret_cast<const float4*>(kvg)[g];
        kvs[(d0 + 0) * 64 + m] = val.x;
        kvs[(d0 + 1) * 64 + m] = val.y;
        kvs[(d0 + 2) * 64 + m] = val.z;
        kvs[(d0 + 3) * 64 + m] = val.w;
    }
    if (tid < 64) kss[tid] = ksum[(b * H + h) * DK + tid];
    int t0 = chunk * 64;
    size_t qbase = (((size_t)b * T + t0) * H + h) * DK;
    {
        int r = tid >> 1;
        int c = (tid & 1) * 32;
        const __half* qg = qp + qbase + (size_t)r * (H * DK) + c;
#pragma unroll
        for (int j = 0; j < 4; ++j) {
            uint4 u = *reinterpret_cast<const uint4*>(qg + j * 8);
            h8_to_f(u, &qs[r][c + j * 8]);
        }
    }
    __syncthreads();

    int mm = tid & 63;
    int hf = tid >> 6;
    for (int r = hf; r < 64; r += 2) {
        float o = 0.f, den = 0.f;
#pragma unroll
        for (int d = 0; d < 64; d += 4) {
            float4 q4 = *reinterpret_cast<const float4*>(&qs[r][d]);
            float4 k4 = *reinterpret_cast<const float4*>(&kss[d]);
            den += q4.x * k4.x + q4.y * k4.y + q4.z * k4.z + q4.w * k4.w;
            o = fmaf(q4.x, kvs[(d + 0) * 64 + mm], o);
            o = fmaf(q4.y, kvs[(d + 1) * 64 + mm], o);
            o = fmaf(q4.z, kvs[(d + 2) * 64 + mm], o);
            o = fmaf(q4.w, kvs[(d + 3) * 64 + mm], o);
        }
        oh[qbase + (size_t)r * (H * DK) + mm] = __float2half(o / (den + 1e-6f));
    }
}

// ---------------------------------------------------------------------------
// Host orchestration
// ---------------------------------------------------------------------------
static inline void mgemm(int mode, const __half* A, const __half* Bw,
                         const float* bias, float* C, __half* Ch, int n, int k) {
    dim3 g(n / 128, M / 128), blk(256);
    switch (mode) {
        case 0: mgemm_kernel<0><<<g, blk, GSMEM>>>(A, Bw, bias, C, Ch, n, k); break;
        case 1: mgemm_kernel<1><<<g, blk, GSMEM>>>(A, Bw, bias, C, Ch, n, k); break;
        case 2: mgemm_kernel<2><<<g, blk, GSMEM>>>(A, Bw, bias, C, Ch, n, k); break;
        case 3: mgemm_kernel<3><<<g, blk, GSMEM>>>(A, Bw, bias, C, Ch, n, k); break;
    }
}

extern "C" void kernel_launch(void* const* d_in, const int* in_sizes, int n_in,
                              void* d_out, int out_size) {
    const float* x_in  = (const float*)d_in[0];
    const float* Wq    = (const float*)d_in[1];
    const float* bq    = (const float*)d_in[2];
    const float* Wk    = (const float*)d_in[3];
    const float* bk    = (const float*)d_in[4];
    const float* Wv    = (const float*)d_in[5];
    const float* bv    = (const float*)d_in[6];
    const float* Wo    = (const float*)d_in[7];
    const float* bo    = (const float*)d_in[8];
    const float* W1    = (const float*)d_in[9];
    const float* b1    = (const float*)d_in[10];
    const float* W2    = (const float*)d_in[11];
    const float* b2    = (const float*)d_in[12];
    const float* ln1_s = (const float*)d_in[13];
    const float* ln1_b = (const float*)d_in[14];
    const float* ln2_s = (const float*)d_in[15];
    const float* ln2_b = (const float*)d_in[16];
    const float* lnf_s = (const float*)d_in[17];
    const float* lnf_b = (const float*)d_in[18];

    cudaFuncSetAttribute(mgemm_kernel<0>, cudaFuncAttributeMaxDynamicSharedMemorySize, GSMEM);
    cudaFuncSetAttribute(mgemm_kernel<1>, cudaFuncAttributeMaxDynamicSharedMemorySize, GSMEM);
    cudaFuncSetAttribute(mgemm_kernel<2>, cudaFuncAttributeMaxDynamicSharedMemorySize, GSMEM);
    cudaFuncSetAttribute(mgemm_kernel<3>, cudaFuncAttributeMaxDynamicSharedMemorySize, GSMEM);

    float* x = (float*)d_out;
    __half *hh, *ohp, *fh, *wh, *q, *k, *v;
    float *kvpp, *kspp, *kvb, *ksb, *pe;
    cudaGetSymbolAddress((void**)&hh,   g_hh);
    cudaGetSymbolAddress((void**)&ohp,  g_oh);
    cudaGetSymbolAddress((void**)&fh,   g_fh);
    cudaGetSymbolAddress((void**)&q,    g_q);
    cudaGetSymbolAddress((void**)&k,    g_k);
    cudaGetSymbolAddress((void**)&v,    g_v);
    cudaGetSymbolAddress((void**)&kvpp, g_kvp);
    cudaGetSymbolAddress((void**)&kspp, g_ksp);
    cudaGetSymbolAddress((void**)&kvb,  g_kv);
    cudaGetSymbolAddress((void**)&ksb,  g_ksum);
    cudaGetSymbolAddress((void**)&pe,   g_pe);
    cudaGetSymbolAddress((void**)&wh,   g_wh);

    // 1 launch: all weight transposes
    transpose_all_kernel<<<NL * 12288, dim3(32, 8)>>>(Wq, Wk, Wv, Wo, W1, W2, wh);

    pe_kernel<<<(T * D) / 256, 256>>>(pe);
    embed_kernel<<<(size_t)M * D / 1024, 256>>>((const float4*)x_in, (const float4*)pe, (float4*)x);

    for (int l = 0; l < NL; ++l) {
        size_t wb  = (size_t)l * WBLK;
        size_t bo_ = (size_t)l * D;
        size_t b1o = (size_t)l * F;
        const __half *wq  = wh + wb;
        const __half *wk  = wh + wb + DD;
        const __half *wv  = wh + wb + 2 * DD;
        const __half *wo_ = wh + wb + 3 * DD;
        const __half *w1  = wh + wb + 4 * DD;
        const __half *w2  = wh + wb + 4 * DD + DF;

        // --- attention block ---
        ln_kernel<1><<<M, 256>>>(x, ln1_s + bo_, ln1_b + bo_, nullptr, hh);
        mgemm(3, hh, wq, bq + bo_, nullptr, q, D, D);   // q = elu+1 -> fp16
        mgemm(3, hh, wk, bk + bo_, nullptr, k, D, D);   // k = elu+1 -> fp16
        mgemm(0, hh, wv, bv + bo_, nullptr, v, D, D);   // v -> fp16
        kv_kernel<<<B * H * NSPL, 256>>>(k, v, kvpp, kspp);
        kvreduce_kernel<<<(B * H * DK * DK) / 256, 256>>>(kvpp, kspp, kvb, ksb);
        attnout_kernel<<<B * H * (T / 64), 128>>>(q, kvb, ksb, ohp);
        mgemm(2, ohp, wo_, bo + bo_, x, nullptr, D, D); // x += attn@Wo (fp32)

        // --- ffn block ---
        ln_kernel<1><<<M, 256>>>(x, ln2_s + bo_, ln2_b + bo_, nullptr, hh);
        mgemm(1, hh, w1, b1 + b1o, nullptr, fh, F, D);  // relu -> fp16
        mgemm(2, fh, w2, b2 + bo_, x, nullptr, D, F);   // x += ffn@W2 (fp32)
    }

    ln_kernel<0><<<M, 256>>>(x, lnf_s, lnf_b, x, nullptr);
}